// round 3
// baseline (speedup 1.0000x reference)
#include <cuda_runtime.h>
#include <cuda_bf16.h>
#include <math.h>
#include <stdint.h>

// ---------------------------------------------------------------------------
// Problem constants
// ---------------------------------------------------------------------------
#define BATCH   4
#define SEQ     2048
#define DIN     4096
#define DPROJ   512
#define DMEM    512
#define ASSIST  512
#define RUN     1536
#define ROWS    (BATCH*SEQ)   // 8192

// ---------------------------------------------------------------------------
// Device scratch
// ---------------------------------------------------------------------------
__device__ float g_Q[(size_t)ROWS*DPROJ];
__device__ float g_K[(size_t)ROWS*DPROJ];
__device__ float g_V[(size_t)ROWS*DPROJ];
__device__ float g_S[(size_t)BATCH*SEQ*SEQ];
__device__ float g_feat[(size_t)ROWS*DPROJ];
__device__ float g_Gz[(size_t)BATCH*RUN*DMEM];
__device__ float g_Gr[(size_t)BATCH*RUN*DMEM];
__device__ float g_Gh[(size_t)BATCH*RUN*DMEM];
__device__ float g_h[BATCH*DMEM];
__device__ float g_rh[BATCH*DMEM];

#define SCAN_BLOCKS 32
// padded epoch flags: one 32B slot per block, monotonic across graph replays
__device__ unsigned g_flagA[SCAN_BLOCKS * 8];
__device__ unsigned g_flagB[SCAN_BLOCKS * 8];

// ---------------------------------------------------------------------------
// SGEMM: C[M,N] = A[M,K] * op(B) (+bias). 128x128x16 tiles, 8x8 microtile
// (two 4-wide column chunks at tx*4 and 64+tx*4 -> Bs LDS conflict 4->2 way),
// double-buffered smem (1 sync / K-tile).
//   transB=0: B[K,N].  transB=1: B[N,K] (C = A*B^T)
//   mode: 0 = plain; 1 = causal tile skip; 2 = K-limit (PV, P lower-tri)
// ---------------------------------------------------------------------------
__global__ void __launch_bounds__(256, 2) sgemm128(
    const float* __restrict__ A, const float* __restrict__ B,
    const float* __restrict__ bias, float* __restrict__ C,
    int M, int N, int K,
    size_t sA, size_t sB, size_t sC,
    int transB, int mode)
{
    constexpr int BM = 128, BN = 128, BK = 16, PAD = 4;
    __shared__ float As[2][BK][BM + PAD];
    __shared__ float Bs[2][BK][BN + PAD];

    int bx = blockIdx.x, by = blockIdx.y, bz = blockIdx.z;
    int rowBase = by * BM, colBase = bx * BN;
    if (mode == 1 && rowBase + BM - 1 < colBase) return;
    int Kend = K;
    if (mode == 2) Kend = (rowBase + BM < K) ? rowBase + BM : K;

    const float* Ab = A + sA * (size_t)bz;
    const float* Bb = B + sB * (size_t)bz;
    float*       Cb = C + sC * (size_t)bz;

    int tid = threadIdx.x;
    int ty = tid >> 4, tx = tid & 15;
    int row0 = ty * 8;
    int c0 = tx * 4, c1 = 64 + tx * 4;     // two 4-wide column chunks

    int arow = tid >> 1, akof = (tid & 1) * 8;
    const float* aptr = Ab + (size_t)(rowBase + arow) * K + akof;

    int bkr = tid >> 4, bnc = (tid & 15) * 8;
    int bnr = tid >> 1, bkof = (tid & 1) * 8;
    const float* bptr = transB
        ? Bb + (size_t)(colBase + bnr) * K + bkof
        : Bb + (size_t)bkr * N + colBase + bnc;

    float acc[8][8];
#pragma unroll
    for (int i = 0; i < 8; i++)
#pragma unroll
        for (int j = 0; j < 8; j++) acc[i][j] = 0.0f;

    int nTiles = Kend / BK;

    {
        float4 a0 = *(const float4*)(aptr);
        float4 a1 = *(const float4*)(aptr + 4);
        As[0][akof + 0][arow] = a0.x; As[0][akof + 1][arow] = a0.y;
        As[0][akof + 2][arow] = a0.z; As[0][akof + 3][arow] = a0.w;
        As[0][akof + 4][arow] = a1.x; As[0][akof + 5][arow] = a1.y;
        As[0][akof + 6][arow] = a1.z; As[0][akof + 7][arow] = a1.w;
        float4 b0 = *(const float4*)(bptr);
        float4 b1 = *(const float4*)(bptr + 4);
        if (!transB) {
            *(float4*)&Bs[0][bkr][bnc]     = b0;
            *(float4*)&Bs[0][bkr][bnc + 4] = b1;
        } else {
            Bs[0][bkof + 0][bnr] = b0.x; Bs[0][bkof + 1][bnr] = b0.y;
            Bs[0][bkof + 2][bnr] = b0.z; Bs[0][bkof + 3][bnr] = b0.w;
            Bs[0][bkof + 4][bnr] = b1.x; Bs[0][bkof + 5][bnr] = b1.y;
            Bs[0][bkof + 6][bnr] = b1.z; Bs[0][bkof + 7][bnr] = b1.w;
        }
    }
    __syncthreads();

    int buf = 0;
    for (int t0 = 0; t0 < nTiles; t0++) {
        float4 na0, na1, nb0, nb1;
        bool nxt = (t0 + 1 < nTiles);
        if (nxt) {
            const float* ap = aptr + (t0 + 1) * BK;
            na0 = *(const float4*)(ap);
            na1 = *(const float4*)(ap + 4);
            const float* bp = transB ? bptr + (t0 + 1) * BK
                                     : bptr + (size_t)(t0 + 1) * BK * N;
            nb0 = *(const float4*)(bp);
            nb1 = *(const float4*)(bp + 4);
        }

#pragma unroll
        for (int kk = 0; kk < BK; kk++) {
            float4 a0 = *(const float4*)&As[buf][kk][row0];
            float4 a1 = *(const float4*)&As[buf][kk][row0 + 4];
            float4 b0 = *(const float4*)&Bs[buf][kk][c0];
            float4 b1 = *(const float4*)&Bs[buf][kk][c1];
            float a[8] = {a0.x, a0.y, a0.z, a0.w, a1.x, a1.y, a1.z, a1.w};
            float b[8] = {b0.x, b0.y, b0.z, b0.w, b1.x, b1.y, b1.z, b1.w};
#pragma unroll
            for (int i = 0; i < 8; i++)
#pragma unroll
                for (int j = 0; j < 8; j++)
                    acc[i][j] = fmaf(a[i], b[j], acc[i][j]);
        }

        if (nxt) {
            int nb = buf ^ 1;
            As[nb][akof + 0][arow] = na0.x; As[nb][akof + 1][arow] = na0.y;
            As[nb][akof + 2][arow] = na0.z; As[nb][akof + 3][arow] = na0.w;
            As[nb][akof + 4][arow] = na1.x; As[nb][akof + 5][arow] = na1.y;
            As[nb][akof + 6][arow] = na1.z; As[nb][akof + 7][arow] = na1.w;
            if (!transB) {
                *(float4*)&Bs[nb][bkr][bnc]     = nb0;
                *(float4*)&Bs[nb][bkr][bnc + 4] = nb1;
            } else {
                Bs[nb][bkof + 0][bnr] = nb0.x; Bs[nb][bkof + 1][bnr] = nb0.y;
                Bs[nb][bkof + 2][bnr] = nb0.z; Bs[nb][bkof + 3][bnr] = nb0.w;
                Bs[nb][bkof + 4][bnr] = nb1.x; Bs[nb][bkof + 5][bnr] = nb1.y;
                Bs[nb][bkof + 6][bnr] = nb1.z; Bs[nb][bkof + 7][bnr] = nb1.w;
            }
        }
        __syncthreads();
        buf ^= 1;
    }

    float4 bv0 = make_float4(0.f, 0.f, 0.f, 0.f);
    float4 bv1 = bv0;
    if (bias) {
        bv0 = *(const float4*)(bias + colBase + c0);
        bv1 = *(const float4*)(bias + colBase + c1);
    }
#pragma unroll
    for (int i = 0; i < 8; i++) {
        size_t row = (size_t)(rowBase + row0 + i);
        float4 o0 = make_float4(acc[i][0] + bv0.x, acc[i][1] + bv0.y,
                                acc[i][2] + bv0.z, acc[i][3] + bv0.w);
        float4 o1 = make_float4(acc[i][4] + bv1.x, acc[i][5] + bv1.y,
                                acc[i][6] + bv1.z, acc[i][7] + bv1.w);
        *(float4*)(Cb + row * N + colBase + c0) = o0;
        *(float4*)(Cb + row * N + colBase + c1) = o1;
    }
}

// ---------------------------------------------------------------------------
// Causal row softmax, in place (single exp pass, smem cache).
// ---------------------------------------------------------------------------
__global__ void softmax_causal_kernel()
{
    int r = blockIdx.x, b = blockIdx.y;
    float* row = g_S + ((size_t)b * SEQ + r) * SEQ;
    int len = r + 1;
    int tid = threadIdx.x;
    __shared__ float buf[SEQ];
    __shared__ float red[256];
    const float inv = rsqrtf(512.0f);

    float m = -3.4e38f;
    for (int i = tid; i < len; i += 256) m = fmaxf(m, row[i]);
    red[tid] = m; __syncthreads();
    for (int s = 128; s; s >>= 1) { if (tid < s) red[tid] = fmaxf(red[tid], red[tid + s]); __syncthreads(); }
    m = red[0] * inv;
    __syncthreads();

    float ssum = 0.0f;
    for (int i = tid; i < len; i += 256) {
        float e = __expf(row[i] * inv - m);
        buf[i] = e;
        ssum += e;
    }
    red[tid] = ssum; __syncthreads();
    for (int s = 128; s; s >>= 1) { if (tid < s) red[tid] += red[tid + s]; __syncthreads(); }
    float denom = 1.0f / red[0];
    __syncthreads();

    for (int i = tid; i < SEQ; i += 256)
        row[i] = (i < len) ? buf[i] * denom : 0.0f;
}

// ---------------------------------------------------------------------------
// Prefix pooling + h0.
// ---------------------------------------------------------------------------
__global__ void pool_kernel(const float* __restrict__ Wscore,
                            const float* __restrict__ Wp2h,
                            const float* __restrict__ bp2h)
{
    int b = blockIdx.x;
    const float* feat = g_feat + (size_t)b * SEQ * DPROJ;
    __shared__ float wsc[512];
    __shared__ float sc[512];
    __shared__ float pooled[512];
    __shared__ float red[256];
    int tid = threadIdx.x;

    for (int i = tid; i < 512; i += 256) wsc[i] = Wscore[i];
    __syncthreads();

    int w = tid >> 5, l = tid & 31;
    for (int u = w; u < ASSIST; u += 8) {
        float s = 0.0f;
        for (int p = l; p < DPROJ; p += 32)
            s = fmaf(feat[(size_t)u * DPROJ + p], wsc[p], s);
#pragma unroll
        for (int o = 16; o; o >>= 1) s += __shfl_xor_sync(0xffffffffu, s, o);
        if (l == 0) sc[u] = s;
    }
    __syncthreads();

    float m = fmaxf(sc[tid], sc[tid + 256]);
    red[tid] = m; __syncthreads();
    for (int s = 128; s; s >>= 1) { if (tid < s) red[tid] = fmaxf(red[tid], red[tid + s]); __syncthreads(); }
    m = red[0]; __syncthreads();

    float e0 = expf(sc[tid] - m), e1 = expf(sc[tid + 256] - m);
    red[tid] = e0 + e1; __syncthreads();
    for (int s = 128; s; s >>= 1) { if (tid < s) red[tid] += red[tid + s]; __syncthreads(); }
    float inv = 1.0f / red[0];
    __syncthreads();
    sc[tid] = e0 * inv; sc[tid + 256] = e1 * inv;
    __syncthreads();

    for (int p = tid; p < DPROJ; p += 256) {
        float acc = 0.0f;
        for (int u = 0; u < ASSIST; u++)
            acc = fmaf(sc[u], feat[(size_t)u * DPROJ + p], acc);
        pooled[p] = acc;
    }
    __syncthreads();

    for (int c = tid; c < DMEM; c += 256) {
        float acc = bp2h[c];
        for (int k = 0; k < DPROJ; k++)
            acc = fmaf(pooled[k], Wp2h[(size_t)k * DMEM + c], acc);
        g_h[b * DMEM + c] = tanhf(acc);
    }
}

__global__ void init_out_kernel(float* __restrict__ out, const float* __restrict__ bmem)
{
    int i = blockIdx.x * blockDim.x + threadIdx.x;
    if (i < BATCH * RUN) out[i] = bmem[0];
}

// ---------------------------------------------------------------------------
// Sequential GRU-style scan. 32 persistent blocks x 256 threads; block owns
// 16 state columns. U slices register-resident (96 regs/thread). Distributed
// epoch-flag barrier: each block publishes its own padded flag; warp 0 polls
// all 32 flags (one per lane) with ballot. Monotonic epochs survive graph
// replays via a base value read at kernel entry.
// ---------------------------------------------------------------------------
#define NC 16
#define HS 520

// All threads enter. Block's global writes must precede the call.
__device__ __forceinline__ void flag_bar(unsigned* flags, unsigned target)
{
    __threadfence();
    __syncthreads();
    if (threadIdx.x == 0)
        *(volatile unsigned*)&flags[blockIdx.x * 8] = target;
    if (threadIdx.x < 32) {
        unsigned mask;
        do {
            unsigned f = *(volatile unsigned*)&flags[threadIdx.x * 8];
            mask = __ballot_sync(0xffffffffu, f == target);
        } while (mask != 0xffffffffu);
        __threadfence();
    }
    __syncthreads();
}

__global__ void __launch_bounds__(256, 1) scan_kernel(
    const float* __restrict__ Uz, const float* __restrict__ Ur,
    const float* __restrict__ Uh, const float* __restrict__ Wmem,
    float* __restrict__ out)
{
    __shared__ float h_s[BATCH * HS];
    __shared__ float rh_s[BATCH * HS];
    __shared__ float part[256 * 9];
    __shared__ float z_s[NC][BATCH];
    __shared__ float wmem_s[NC];

    int tid = threadIdx.x;
    int c   = tid & 15;
    int seg = tid >> 4;          // 16 segments of 32 k
    int cglob = blockIdx.x * NC + c;
    int kbase = seg * 32;

    float uz[32], ur[32], uh[32];
#pragma unroll
    for (int i = 0; i < 32; i++) {
        uz[i] = Uz[(size_t)(kbase + i) * DMEM + cglob];
        ur[i] = Ur[(size_t)(kbase + i) * DMEM + cglob];
        uh[i] = Uh[(size_t)(kbase + i) * DMEM + cglob];
    }
    if (seg == 0) wmem_s[c] = Wmem[cglob];

    // epoch base (uniform across blocks between runs)
    unsigned baseA = *(volatile unsigned*)&g_flagA[blockIdx.x * 8];
    unsigned baseB = *(volatile unsigned*)&g_flagB[blockIdx.x * 8];

    {
        int idx = tid * 8;
#pragma unroll
        for (int j = 0; j < 8; j++) {
            int ii = idx + j;
            h_s[(ii >> 9) * HS + (ii & 511)] = __ldcg(&g_h[ii]);
        }
    }
    __syncthreads();

    const float dtc = 1.0f / 1535.0f;

    for (int t = 0; t < RUN; t++) {
        float dtv = (t == 0) ? 0.0f : dtc;

        float gA = 0.0f, gH = 0.0f;
        if (tid < 128) {
            int mat = tid >> 6, cc = (tid >> 2) & 15, b = tid & 3;
            const float* P = mat ? g_Gr : g_Gz;
            gA = __ldg(&P[((size_t)(b * RUN + t)) * DMEM + blockIdx.x * NC + cc]);
        }
        if (tid < 64) {
            int cc = tid >> 2, b = tid & 3;
            gH = __ldg(&g_Gh[((size_t)(b * RUN + t)) * DMEM + blockIdx.x * NC + cc]);
        }

        // ---- phase A: partial dots for z and r ----
        float pz[4] = {0, 0, 0, 0}, pr[4] = {0, 0, 0, 0};
#pragma unroll
        for (int i = 0; i < 32; i++) {
            float a = uz[i], rr = ur[i];
#pragma unroll
            for (int b = 0; b < 4; b++) {
                float hv = h_s[b * HS + kbase + i];
                pz[b] = fmaf(hv, a, pz[b]);
                pr[b] = fmaf(hv, rr, pr[b]);
            }
        }
#pragma unroll
        for (int b = 0; b < 4; b++) {
            part[tid * 9 + b]     = pz[b];
            part[tid * 9 + 4 + b] = pr[b];
        }
        __syncthreads();

        if (tid < 128) {
            int mat = tid >> 6, cc = (tid >> 2) & 15, b = tid & 3;
            float s = 0.0f;
#pragma unroll
            for (int sg = 0; sg < 16; sg++)
                s += part[(cc + (sg << 4)) * 9 + mat * 4 + b];
            float v = gA + s;
            float sig = 1.0f / (1.0f + expf(-v));
            if (mat == 0) {
                z_s[cc][b] = sig;
            } else {
                int cg = blockIdx.x * NC + cc;
                g_rh[b * DMEM + cg] = sig * h_s[b * HS + cg];
            }
        }
        flag_bar(g_flagA, baseA + (unsigned)t + 1u);

        // gather full r*h (written by other SMs; bypass L1)
        {
            int idx = tid * 8;
#pragma unroll
            for (int j = 0; j < 8; j++) {
                int ii = idx + j;
                rh_s[(ii >> 9) * HS + (ii & 511)] = __ldcg(&g_rh[ii]);
            }
        }
        __syncthreads();

        // ---- phase B: candidate, state update, logit ----
        float ph[4] = {0, 0, 0, 0};
#pragma unroll
        for (int i = 0; i < 32; i++) {
            float u = uh[i];
#pragma unroll
            for (int b = 0; b < 4; b++)
                ph[b] = fmaf(rh_s[b * HS + kbase + i], u, ph[b]);
        }
#pragma unroll
        for (int b = 0; b < 4; b++) part[tid * 9 + b] = ph[b];
        __syncthreads();

        if (tid < 64) {                 // warps 0 and 1, fully active
            int cc = tid >> 2, b = tid & 3;
            float s = 0.0f;
#pragma unroll
            for (int sg = 0; sg < 16; sg++)
                s += part[(cc + (sg << 4)) * 9 + b];
            int cg = blockIdx.x * NC + cc;
            float hh   = tanhf(gH + s);
            float hold = h_s[b * HS + cg];
            float zv   = z_s[cc][b];
            float hnew = hold + zv * (hh - hold);
            float hout = hnew + dtv * (hnew - hold);
            g_h[b * DMEM + cg] = hout;
            // warp-level reduce over cc (lanes cc*4+b within each warp)
            float lv = hout * wmem_s[cc];
            lv += __shfl_xor_sync(0xffffffffu, lv, 4);
            lv += __shfl_xor_sync(0xffffffffu, lv, 8);
            lv += __shfl_xor_sync(0xffffffffu, lv, 16);
            if ((tid & 31) < 4)
                atomicAdd(&out[b * RUN + t], lv);
        }
        flag_bar(g_flagB, baseB + (unsigned)t + 1u);

        // reload full h
        {
            int idx = tid * 8;
#pragma unroll
            for (int j = 0; j < 8; j++) {
                int ii = idx + j;
                h_s[(ii >> 9) * HS + (ii & 511)] = __ldcg(&g_h[ii]);
            }
        }
        __syncthreads();
    }
}

// ---------------------------------------------------------------------------
// Host
// ---------------------------------------------------------------------------
extern "C" void kernel_launch(void* const* d_in, const int* in_sizes, int n_in,
                              void* d_out, int out_size)
{
    const float* x      = (const float*)d_in[0];
    const float* Wq     = (const float*)d_in[1];
    const float* bq     = (const float*)d_in[2];
    const float* Wk     = (const float*)d_in[3];
    const float* bk     = (const float*)d_in[4];
    const float* Wv     = (const float*)d_in[5];
    const float* bv     = (const float*)d_in[6];
    const float* Wz     = (const float*)d_in[7];
    const float* Uz     = (const float*)d_in[8];
    const float* bz     = (const float*)d_in[9];
    const float* Wr     = (const float*)d_in[10];
    const float* Ur     = (const float*)d_in[11];
    const float* br     = (const float*)d_in[12];
    const float* Wh     = (const float*)d_in[13];
    const float* Uh     = (const float*)d_in[14];
    const float* bh     = (const float*)d_in[15];
    const float* Wmem   = (const float*)d_in[16];
    const float* bmem   = (const float*)d_in[17];
    const float* Wp2h   = (const float*)d_in[18];
    const float* bp2h   = (const float*)d_in[19];
    const float* Wscore = (const float*)d_in[20];
    (void)in_sizes; (void)n_in;
    float* out = (float*)d_out;

    float *pQ, *pK, *pV, *pS, *pF, *pGz, *pGr, *pGh;
    cudaGetSymbolAddress((void**)&pQ,  g_Q);
    cudaGetSymbolAddress((void**)&pK,  g_K);
    cudaGetSymbolAddress((void**)&pV,  g_V);
    cudaGetSymbolAddress((void**)&pS,  g_S);
    cudaGetSymbolAddress((void**)&pF,  g_feat);
    cudaGetSymbolAddress((void**)&pGz, g_Gz);
    cudaGetSymbolAddress((void**)&pGr, g_Gr);
    cudaGetSymbolAddress((void**)&pGh, g_Gh);

    dim3 t256(256);

    // QKV projections
    {
        dim3 g(DPROJ / 128, ROWS / 128, 1);
        sgemm128<<<g, t256>>>(x, Wq, bq, pQ, ROWS, DPROJ, DIN, 0, 0, 0, 0, 0);
        sgemm128<<<g, t256>>>(x, Wk, bk, pK, ROWS, DPROJ, DIN, 0, 0, 0, 0, 0);
        sgemm128<<<g, t256>>>(x, Wv, bv, pV, ROWS, DPROJ, DIN, 0, 0, 0, 0, 0);
    }

    // scores = Q K^T (causal tile skip)
    {
        dim3 g(SEQ / 128, SEQ / 128, BATCH);
        sgemm128<<<g, t256>>>(pQ, pK, nullptr, pS, SEQ, SEQ, DPROJ,
                              (size_t)SEQ * DPROJ, (size_t)SEQ * DPROJ,
                              (size_t)SEQ * SEQ, 1, 1);
    }

    softmax_causal_kernel<<<dim3(SEQ, BATCH), t256>>>();

    // feat = P V (K-limited: P lower-triangular)
    {
        dim3 g(DPROJ / 128, SEQ / 128, BATCH);
        sgemm128<<<g, t256>>>(pS, pV, nullptr, pF, SEQ, DPROJ, SEQ,
                              (size_t)SEQ * SEQ, (size_t)SEQ * DPROJ,
                              (size_t)SEQ * DPROJ, 0, 2);
    }

    pool_kernel<<<BATCH, t256>>>(Wscore, Wp2h, bp2h);

    // G* = feat_assist @ W* + b*
    {
        dim3 g(DMEM / 128, RUN / 128, BATCH);
        const float* Aoff = pF + (size_t)ASSIST * DPROJ;
        sgemm128<<<g, t256>>>(Aoff, Wz, bz, pGz, RUN, DMEM, DPROJ,
                              (size_t)SEQ * DPROJ, 0, (size_t)RUN * DMEM, 0, 0);
        sgemm128<<<g, t256>>>(Aoff, Wr, br, pGr, RUN, DMEM, DPROJ,
                              (size_t)SEQ * DPROJ, 0, (size_t)RUN * DMEM, 0, 0);
        sgemm128<<<g, t256>>>(Aoff, Wh, bh, pGh, RUN, DMEM, DPROJ,
                              (size_t)SEQ * DPROJ, 0, (size_t)RUN * DMEM, 0, 0);
    }

    init_out_kernel<<<(BATCH * RUN + 255) / 256, t256>>>(out, bmem);
    scan_kernel<<<SCAN_BLOCKS, t256>>>(Uz, Ur, Uh, Wmem, out);

    (void)out_size;
}

// round 4
// speedup vs baseline: 1.1754x; 1.1754x over previous
#include <cuda_runtime.h>
#include <cuda_bf16.h>
#include <math.h>
#include <stdint.h>

// ---------------------------------------------------------------------------
// Problem constants
// ---------------------------------------------------------------------------
#define BATCH   4
#define SEQ     2048
#define DIN     4096
#define DPROJ   512
#define DMEM    512
#define ASSIST  512
#define RUN     1536
#define ROWS    (BATCH*SEQ)   // 8192

// ---------------------------------------------------------------------------
// Device scratch
// ---------------------------------------------------------------------------
__device__ float g_Q[(size_t)ROWS*DPROJ];
__device__ float g_K[(size_t)ROWS*DPROJ];
__device__ float g_V[(size_t)ROWS*DPROJ];
__device__ float g_S[(size_t)BATCH*SEQ*SEQ];
__device__ float g_feat[(size_t)ROWS*DPROJ];
__device__ float g_Gz[(size_t)BATCH*RUN*DMEM];
__device__ float g_Gr[(size_t)BATCH*RUN*DMEM];
__device__ float g_Gh[(size_t)BATCH*RUN*DMEM];
__device__ float g_h[BATCH*DMEM];
__device__ float g_rh[BATCH*DMEM];

#define SCAN_BLOCKS 32
// padded epoch flags: one 32B slot per block, monotonic across graph replays
__device__ unsigned g_flagA[SCAN_BLOCKS * 8];
__device__ unsigned g_flagB[SCAN_BLOCKS * 8];

// ---------------------------------------------------------------------------
// GPU-scope acquire/release primitives (NOT volatile -> NOT sys-scope)
// ---------------------------------------------------------------------------
__device__ __forceinline__ void st_release_gpu(unsigned* p, unsigned v) {
    asm volatile("st.release.gpu.global.u32 [%0], %1;" :: "l"(p), "r"(v) : "memory");
}
__device__ __forceinline__ unsigned ld_acquire_gpu(const unsigned* p) {
    unsigned v;
    asm volatile("ld.acquire.gpu.global.u32 %0, [%1];" : "=r"(v) : "l"(p) : "memory");
    return v;
}
__device__ __forceinline__ unsigned ld_relaxed_gpu(const unsigned* p) {
    unsigned v;
    asm volatile("ld.relaxed.gpu.global.u32 %0, [%1];" : "=r"(v) : "l"(p) : "memory");
    return v;
}

// ---------------------------------------------------------------------------
// SGEMM: C[M,N] = A[M,K] * op(B) (+bias). 128x128x16 tiles, 8x8 microtile
// (two 4-wide column chunks), double-buffered smem (1 sync / K-tile).
//   transB=0: B[K,N].  transB=1: B[N,K] (C = A*B^T)
//   mode: 0 = plain; 1 = causal tile skip; 2 = K-limit (PV, P lower-tri)
// ---------------------------------------------------------------------------
__global__ void __launch_bounds__(256, 2) sgemm128(
    const float* __restrict__ A, const float* __restrict__ B,
    const float* __restrict__ bias, float* __restrict__ C,
    int M, int N, int K,
    size_t sA, size_t sB, size_t sC,
    int transB, int mode)
{
    constexpr int BM = 128, BN = 128, BK = 16, PAD = 4;
    __shared__ float As[2][BK][BM + PAD];
    __shared__ float Bs[2][BK][BN + PAD];

    int bx = blockIdx.x, by = blockIdx.y, bz = blockIdx.z;
    int rowBase = by * BM, colBase = bx * BN;
    if (mode == 1 && rowBase + BM - 1 < colBase) return;
    int Kend = K;
    if (mode == 2) Kend = (rowBase + BM < K) ? rowBase + BM : K;

    const float* Ab = A + sA * (size_t)bz;
    const float* Bb = B + sB * (size_t)bz;
    float*       Cb = C + sC * (size_t)bz;

    int tid = threadIdx.x;
    int ty = tid >> 4, tx = tid & 15;
    int row0 = ty * 8;
    int c0 = tx * 4, c1 = 64 + tx * 4;

    int arow = tid >> 1, akof = (tid & 1) * 8;
    const float* aptr = Ab + (size_t)(rowBase + arow) * K + akof;

    int bkr = tid >> 4, bnc = (tid & 15) * 8;
    int bnr = tid >> 1, bkof = (tid & 1) * 8;
    const float* bptr = transB
        ? Bb + (size_t)(colBase + bnr) * K + bkof
        : Bb + (size_t)bkr * N + colBase + bnc;

    float acc[8][8];
#pragma unroll
    for (int i = 0; i < 8; i++)
#pragma unroll
        for (int j = 0; j < 8; j++) acc[i][j] = 0.0f;

    int nTiles = Kend / BK;

    {
        float4 a0 = *(const float4*)(aptr);
        float4 a1 = *(const float4*)(aptr + 4);
        As[0][akof + 0][arow] = a0.x; As[0][akof + 1][arow] = a0.y;
        As[0][akof + 2][arow] = a0.z; As[0][akof + 3][arow] = a0.w;
        As[0][akof + 4][arow] = a1.x; As[0][akof + 5][arow] = a1.y;
        As[0][akof + 6][arow] = a1.z; As[0][akof + 7][arow] = a1.w;
        float4 b0 = *(const float4*)(bptr);
        float4 b1 = *(const float4*)(bptr + 4);
        if (!transB) {
            *(float4*)&Bs[0][bkr][bnc]     = b0;
            *(float4*)&Bs[0][bkr][bnc + 4] = b1;
        } else {
            Bs[0][bkof + 0][bnr] = b0.x; Bs[0][bkof + 1][bnr] = b0.y;
            Bs[0][bkof + 2][bnr] = b0.z; Bs[0][bkof + 3][bnr] = b0.w;
            Bs[0][bkof + 4][bnr] = b1.x; Bs[0][bkof + 5][bnr] = b1.y;
            Bs[0][bkof + 6][bnr] = b1.z; Bs[0][bkof + 7][bnr] = b1.w;
        }
    }
    __syncthreads();

    int buf = 0;
    for (int t0 = 0; t0 < nTiles; t0++) {
        float4 na0, na1, nb0, nb1;
        bool nxt = (t0 + 1 < nTiles);
        if (nxt) {
            const float* ap = aptr + (t0 + 1) * BK;
            na0 = *(const float4*)(ap);
            na1 = *(const float4*)(ap + 4);
            const float* bp = transB ? bptr + (t0 + 1) * BK
                                     : bptr + (size_t)(t0 + 1) * BK * N;
            nb0 = *(const float4*)(bp);
            nb1 = *(const float4*)(bp + 4);
        }

#pragma unroll
        for (int kk = 0; kk < BK; kk++) {
            float4 a0 = *(const float4*)&As[buf][kk][row0];
            float4 a1 = *(const float4*)&As[buf][kk][row0 + 4];
            float4 b0 = *(const float4*)&Bs[buf][kk][c0];
            float4 b1 = *(const float4*)&Bs[buf][kk][c1];
            float a[8] = {a0.x, a0.y, a0.z, a0.w, a1.x, a1.y, a1.z, a1.w};
            float b[8] = {b0.x, b0.y, b0.z, b0.w, b1.x, b1.y, b1.z, b1.w};
#pragma unroll
            for (int i = 0; i < 8; i++)
#pragma unroll
                for (int j = 0; j < 8; j++)
                    acc[i][j] = fmaf(a[i], b[j], acc[i][j]);
        }

        if (nxt) {
            int nb = buf ^ 1;
            As[nb][akof + 0][arow] = na0.x; As[nb][akof + 1][arow] = na0.y;
            As[nb][akof + 2][arow] = na0.z; As[nb][akof + 3][arow] = na0.w;
            As[nb][akof + 4][arow] = na1.x; As[nb][akof + 5][arow] = na1.y;
            As[nb][akof + 6][arow] = na1.z; As[nb][akof + 7][arow] = na1.w;
            if (!transB) {
                *(float4*)&Bs[nb][bkr][bnc]     = nb0;
                *(float4*)&Bs[nb][bkr][bnc + 4] = nb1;
            } else {
                Bs[nb][bkof + 0][bnr] = nb0.x; Bs[nb][bkof + 1][bnr] = nb0.y;
                Bs[nb][bkof + 2][bnr] = nb0.z; Bs[nb][bkof + 3][bnr] = nb0.w;
                Bs[nb][bkof + 4][bnr] = nb1.x; Bs[nb][bkof + 5][bnr] = nb1.y;
                Bs[nb][bkof + 6][bnr] = nb1.z; Bs[nb][bkof + 7][bnr] = nb1.w;
            }
        }
        __syncthreads();
        buf ^= 1;
    }

    float4 bv0 = make_float4(0.f, 0.f, 0.f, 0.f);
    float4 bv1 = bv0;
    if (bias) {
        bv0 = *(const float4*)(bias + colBase + c0);
        bv1 = *(const float4*)(bias + colBase + c1);
    }
#pragma unroll
    for (int i = 0; i < 8; i++) {
        size_t row = (size_t)(rowBase + row0 + i);
        float4 o0 = make_float4(acc[i][0] + bv0.x, acc[i][1] + bv0.y,
                                acc[i][2] + bv0.z, acc[i][3] + bv0.w);
        float4 o1 = make_float4(acc[i][4] + bv1.x, acc[i][5] + bv1.y,
                                acc[i][6] + bv1.z, acc[i][7] + bv1.w);
        *(float4*)(Cb + row * N + colBase + c0) = o0;
        *(float4*)(Cb + row * N + colBase + c1) = o1;
    }
}

// ---------------------------------------------------------------------------
// Causal row softmax, in place (single exp pass, smem cache).
// ---------------------------------------------------------------------------
__global__ void softmax_causal_kernel()
{
    int r = blockIdx.x, b = blockIdx.y;
    float* row = g_S + ((size_t)b * SEQ + r) * SEQ;
    int len = r + 1;
    int tid = threadIdx.x;
    __shared__ float buf[SEQ];
    __shared__ float red[256];
    const float inv = rsqrtf(512.0f);

    float m = -3.4e38f;
    for (int i = tid; i < len; i += 256) m = fmaxf(m, row[i]);
    red[tid] = m; __syncthreads();
    for (int s = 128; s; s >>= 1) { if (tid < s) red[tid] = fmaxf(red[tid], red[tid + s]); __syncthreads(); }
    m = red[0] * inv;
    __syncthreads();

    float ssum = 0.0f;
    for (int i = tid; i < len; i += 256) {
        float e = __expf(row[i] * inv - m);
        buf[i] = e;
        ssum += e;
    }
    red[tid] = ssum; __syncthreads();
    for (int s = 128; s; s >>= 1) { if (tid < s) red[tid] += red[tid + s]; __syncthreads(); }
    float denom = 1.0f / red[0];
    __syncthreads();

    for (int i = tid; i < SEQ; i += 256)
        row[i] = (i < len) ? buf[i] * denom : 0.0f;
}

// ---------------------------------------------------------------------------
// Prefix pooling + h0.
// ---------------------------------------------------------------------------
__global__ void pool_kernel(const float* __restrict__ Wscore,
                            const float* __restrict__ Wp2h,
                            const float* __restrict__ bp2h)
{
    int b = blockIdx.x;
    const float* feat = g_feat + (size_t)b * SEQ * DPROJ;
    __shared__ float wsc[512];
    __shared__ float sc[512];
    __shared__ float pooled[512];
    __shared__ float red[256];
    int tid = threadIdx.x;

    for (int i = tid; i < 512; i += 256) wsc[i] = Wscore[i];
    __syncthreads();

    int w = tid >> 5, l = tid & 31;
    for (int u = w; u < ASSIST; u += 8) {
        float s = 0.0f;
        for (int p = l; p < DPROJ; p += 32)
            s = fmaf(feat[(size_t)u * DPROJ + p], wsc[p], s);
#pragma unroll
        for (int o = 16; o; o >>= 1) s += __shfl_xor_sync(0xffffffffu, s, o);
        if (l == 0) sc[u] = s;
    }
    __syncthreads();

    float m = fmaxf(sc[tid], sc[tid + 256]);
    red[tid] = m; __syncthreads();
    for (int s = 128; s; s >>= 1) { if (tid < s) red[tid] = fmaxf(red[tid], red[tid + s]); __syncthreads(); }
    m = red[0]; __syncthreads();

    float e0 = expf(sc[tid] - m), e1 = expf(sc[tid + 256] - m);
    red[tid] = e0 + e1; __syncthreads();
    for (int s = 128; s; s >>= 1) { if (tid < s) red[tid] += red[tid + s]; __syncthreads(); }
    float inv = 1.0f / red[0];
    __syncthreads();
    sc[tid] = e0 * inv; sc[tid + 256] = e1 * inv;
    __syncthreads();

    for (int p = tid; p < DPROJ; p += 256) {
        float acc = 0.0f;
        for (int u = 0; u < ASSIST; u++)
            acc = fmaf(sc[u], feat[(size_t)u * DPROJ + p], acc);
        pooled[p] = acc;
    }
    __syncthreads();

    for (int c = tid; c < DMEM; c += 256) {
        float acc = bp2h[c];
        for (int k = 0; k < DPROJ; k++)
            acc = fmaf(pooled[k], Wp2h[(size_t)k * DMEM + c], acc);
        g_h[b * DMEM + c] = tanhf(acc);
    }
}

__global__ void init_out_kernel(float* __restrict__ out, const float* __restrict__ bmem)
{
    int i = blockIdx.x * blockDim.x + threadIdx.x;
    if (i < BATCH * RUN) out[i] = bmem[0];
}

// ---------------------------------------------------------------------------
// Sequential GRU-style scan. 32 persistent blocks x 256 threads; block owns
// 16 state columns. U slices register-resident. Barriers use GPU-scope
// release/acquire flags only (no volatile, no threadfence -> no SYS scope).
// ---------------------------------------------------------------------------
#define NC 16
#define HS 520

// All threads enter. Block's data STGs precede the __syncthreads, thread0's
// release-store then carries block-wide happens-before to acquiring pollers.
__device__ __forceinline__ void flag_bar(unsigned* flags, unsigned target)
{
    __syncthreads();
    if (threadIdx.x == 0)
        st_release_gpu(&flags[blockIdx.x * 8], target);
    if (threadIdx.x < 32) {
        unsigned mask;
        do {
            unsigned f = ld_acquire_gpu(&flags[threadIdx.x * 8]);
            mask = __ballot_sync(0xffffffffu, (int)(f - target) >= 0);
        } while (mask != 0xffffffffu);
    }
    __syncthreads();
}

__global__ void __launch_bounds__(256, 1) scan_kernel(
    const float* __restrict__ Uz, const float* __restrict__ Ur,
    const float* __restrict__ Uh, const float* __restrict__ Wmem,
    float* __restrict__ out)
{
    __shared__ float h_s[BATCH * HS];
    __shared__ float rh_s[BATCH * HS];
    __shared__ float part[256 * 9];
    __shared__ float z_s[NC][BATCH];
    __shared__ float wmem_s[NC];

    int tid = threadIdx.x;
    int c   = tid & 15;
    int seg = tid >> 4;          // 16 segments of 32 k
    int cglob = blockIdx.x * NC + c;
    int kbase = seg * 32;

    float uz[32], ur[32], uh[32];
#pragma unroll
    for (int i = 0; i < 32; i++) {
        uz[i] = Uz[(size_t)(kbase + i) * DMEM + cglob];
        ur[i] = Ur[(size_t)(kbase + i) * DMEM + cglob];
        uh[i] = Uh[(size_t)(kbase + i) * DMEM + cglob];
    }
    if (seg == 0) wmem_s[c] = Wmem[cglob];

    // epoch base: own slot's last value (uniform across blocks between runs)
    unsigned baseA = ld_relaxed_gpu(&g_flagA[blockIdx.x * 8]);
    unsigned baseB = ld_relaxed_gpu(&g_flagB[blockIdx.x * 8]);

    {
        int idx = tid * 8;
#pragma unroll
        for (int j = 0; j < 8; j++) {
            int ii = idx + j;
            h_s[(ii >> 9) * HS + (ii & 511)] = __ldcg(&g_h[ii]);
        }
    }
    __syncthreads();

    const float dtc = 1.0f / 1535.0f;

    for (int t = 0; t < RUN; t++) {
        float dtv = (t == 0) ? 0.0f : dtc;

        float gA = 0.0f, gH = 0.0f;
        if (tid < 128) {
            int mat = tid >> 6, cc = (tid >> 2) & 15, b = tid & 3;
            const float* P = mat ? g_Gr : g_Gz;
            gA = __ldg(&P[((size_t)(b * RUN + t)) * DMEM + blockIdx.x * NC + cc]);
        }
        if (tid < 64) {
            int cc = tid >> 2, b = tid & 3;
            gH = __ldg(&g_Gh[((size_t)(b * RUN + t)) * DMEM + blockIdx.x * NC + cc]);
        }

        // ---- phase A: partial dots for z and r ----
        float pz[4] = {0, 0, 0, 0}, pr[4] = {0, 0, 0, 0};
#pragma unroll
        for (int i = 0; i < 32; i++) {
            float a = uz[i], rr = ur[i];
#pragma unroll
            for (int b = 0; b < 4; b++) {
                float hv = h_s[b * HS + kbase + i];
                pz[b] = fmaf(hv, a, pz[b]);
                pr[b] = fmaf(hv, rr, pr[b]);
            }
        }
#pragma unroll
        for (int b = 0; b < 4; b++) {
            part[tid * 9 + b]     = pz[b];
            part[tid * 9 + 4 + b] = pr[b];
        }
        __syncthreads();

        if (tid < 128) {
            int mat = tid >> 6, cc = (tid >> 2) & 15, b = tid & 3;
            float s = 0.0f;
#pragma unroll
            for (int sg = 0; sg < 16; sg++)
                s += part[(cc + (sg << 4)) * 9 + mat * 4 + b];
            float v = gA + s;
            float sig = 1.0f / (1.0f + expf(-v));
            if (mat == 0) {
                z_s[cc][b] = sig;
            } else {
                int cg = blockIdx.x * NC + cc;
                g_rh[b * DMEM + cg] = sig * h_s[b * HS + cg];
            }
        }
        flag_bar(g_flagA, baseA + (unsigned)t + 1u);

        // gather full r*h (written by other SMs; bypass L1)
        {
            int idx = tid * 8;
#pragma unroll
            for (int j = 0; j < 8; j++) {
                int ii = idx + j;
                rh_s[(ii >> 9) * HS + (ii & 511)] = __ldcg(&g_rh[ii]);
            }
        }
        __syncthreads();

        // ---- phase B: candidate, state update, logit ----
        float ph[4] = {0, 0, 0, 0};
#pragma unroll
        for (int i = 0; i < 32; i++) {
            float u = uh[i];
#pragma unroll
            for (int b = 0; b < 4; b++)
                ph[b] = fmaf(rh_s[b * HS + kbase + i], u, ph[b]);
        }
#pragma unroll
        for (int b = 0; b < 4; b++) part[tid * 9 + b] = ph[b];
        __syncthreads();

        if (tid < 64) {
            int cc = tid >> 2, b = tid & 3;
            float s = 0.0f;
#pragma unroll
            for (int sg = 0; sg < 16; sg++)
                s += part[(cc + (sg << 4)) * 9 + b];
            int cg = blockIdx.x * NC + cc;
            float hh   = tanhf(gH + s);
            float hold = h_s[b * HS + cg];
            float zv   = z_s[cc][b];
            float hnew = hold + zv * (hh - hold);
            float hout = hnew + dtv * (hnew - hold);
            g_h[b * DMEM + cg] = hout;
            float lv = hout * wmem_s[cc];
            lv += __shfl_xor_sync(0xffffffffu, lv, 4);
            lv += __shfl_xor_sync(0xffffffffu, lv, 8);
            lv += __shfl_xor_sync(0xffffffffu, lv, 16);
            if ((tid & 31) < 4)
                atomicAdd(&out[b * RUN + t], lv);
        }
        flag_bar(g_flagB, baseB + (unsigned)t + 1u);

        // reload full h
        {
            int idx = tid * 8;
#pragma unroll
            for (int j = 0; j < 8; j++) {
                int ii = idx + j;
                h_s[(ii >> 9) * HS + (ii & 511)] = __ldcg(&g_h[ii]);
            }
        }
        __syncthreads();
    }
}

// ---------------------------------------------------------------------------
// Host
// ---------------------------------------------------------------------------
extern "C" void kernel_launch(void* const* d_in, const int* in_sizes, int n_in,
                              void* d_out, int out_size)
{
    const float* x      = (const float*)d_in[0];
    const float* Wq     = (const float*)d_in[1];
    const float* bq     = (const float*)d_in[2];
    const float* Wk     = (const float*)d_in[3];
    const float* bk     = (const float*)d_in[4];
    const float* Wv     = (const float*)d_in[5];
    const float* bv     = (const float*)d_in[6];
    const float* Wz     = (const float*)d_in[7];
    const float* Uz     = (const float*)d_in[8];
    const float* bz     = (const float*)d_in[9];
    const float* Wr     = (const float*)d_in[10];
    const float* Ur     = (const float*)d_in[11];
    const float* br     = (const float*)d_in[12];
    const float* Wh     = (const float*)d_in[13];
    const float* Uh     = (const float*)d_in[14];
    const float* bh     = (const float*)d_in[15];
    const float* Wmem   = (const float*)d_in[16];
    const float* bmem   = (const float*)d_in[17];
    const float* Wp2h   = (const float*)d_in[18];
    const float* bp2h   = (const float*)d_in[19];
    const float* Wscore = (const float*)d_in[20];
    (void)in_sizes; (void)n_in;
    float* out = (float*)d_out;

    float *pQ, *pK, *pV, *pS, *pF, *pGz, *pGr, *pGh;
    cudaGetSymbolAddress((void**)&pQ,  g_Q);
    cudaGetSymbolAddress((void**)&pK,  g_K);
    cudaGetSymbolAddress((void**)&pV,  g_V);
    cudaGetSymbolAddress((void**)&pS,  g_S);
    cudaGetSymbolAddress((void**)&pF,  g_feat);
    cudaGetSymbolAddress((void**)&pGz, g_Gz);
    cudaGetSymbolAddress((void**)&pGr, g_Gr);
    cudaGetSymbolAddress((void**)&pGh, g_Gh);

    dim3 t256(256);

    // QKV projections
    {
        dim3 g(DPROJ / 128, ROWS / 128, 1);
        sgemm128<<<g, t256>>>(x, Wq, bq, pQ, ROWS, DPROJ, DIN, 0, 0, 0, 0, 0);
        sgemm128<<<g, t256>>>(x, Wk, bk, pK, ROWS, DPROJ, DIN, 0, 0, 0, 0, 0);
        sgemm128<<<g, t256>>>(x, Wv, bv, pV, ROWS, DPROJ, DIN, 0, 0, 0, 0, 0);
    }

    // scores = Q K^T (causal tile skip)
    {
        dim3 g(SEQ / 128, SEQ / 128, BATCH);
        sgemm128<<<g, t256>>>(pQ, pK, nullptr, pS, SEQ, SEQ, DPROJ,
                              (size_t)SEQ * DPROJ, (size_t)SEQ * DPROJ,
                              (size_t)SEQ * SEQ, 1, 1);
    }

    softmax_causal_kernel<<<dim3(SEQ, BATCH), t256>>>();

    // feat = P V (K-limited: P lower-triangular)
    {
        dim3 g(DPROJ / 128, SEQ / 128, BATCH);
        sgemm128<<<g, t256>>>(pS, pV, nullptr, pF, SEQ, DPROJ, SEQ,
                              (size_t)SEQ * SEQ, (size_t)SEQ * DPROJ,
                              (size_t)SEQ * DPROJ, 0, 2);
    }

    pool_kernel<<<BATCH, t256>>>(Wscore, Wp2h, bp2h);

    // G* = feat_assist @ W* + b*
    {
        dim3 g(DMEM / 128, RUN / 128, BATCH);
        const float* Aoff = pF + (size_t)ASSIST * DPROJ;
        sgemm128<<<g, t256>>>(Aoff, Wz, bz, pGz, RUN, DMEM, DPROJ,
                              (size_t)SEQ * DPROJ, 0, (size_t)RUN * DMEM, 0, 0);
        sgemm128<<<g, t256>>>(Aoff, Wr, br, pGr, RUN, DMEM, DPROJ,
                              (size_t)SEQ * DPROJ, 0, (size_t)RUN * DMEM, 0, 0);
        sgemm128<<<g, t256>>>(Aoff, Wh, bh, pGh, RUN, DMEM, DPROJ,
                              (size_t)SEQ * DPROJ, 0, (size_t)RUN * DMEM, 0, 0);
    }

    init_out_kernel<<<(BATCH * RUN + 255) / 256, t256>>>(out, bmem);
    scan_kernel<<<SCAN_BLOCKS, t256>>>(Uz, Ur, Uh, Wmem, out);

    (void)out_size;
}

// round 5
// speedup vs baseline: 2.0122x; 1.7120x over previous
#include <cuda_runtime.h>
#include <cuda_bf16.h>
#include <math.h>
#include <stdint.h>

// ---------------------------------------------------------------------------
// Problem constants
// ---------------------------------------------------------------------------
#define BATCH   4
#define SEQ     2048
#define DIN     4096
#define DPROJ   512
#define DMEM    512
#define ASSIST  512
#define RUN     1536
#define ROWS    (BATCH*SEQ)   // 8192

// ---------------------------------------------------------------------------
// Device scratch
// ---------------------------------------------------------------------------
__device__ float g_Q[(size_t)ROWS*DPROJ];
__device__ float g_K[(size_t)ROWS*DPROJ];
__device__ float g_V[(size_t)ROWS*DPROJ];
__device__ float g_S[(size_t)BATCH*SEQ*SEQ];
__device__ float g_feat[(size_t)ROWS*DPROJ];
__device__ float g_Gz[(size_t)BATCH*RUN*DMEM];
__device__ float g_Gr[(size_t)BATCH*RUN*DMEM];
__device__ float g_Gh[(size_t)BATCH*RUN*DMEM];
__device__ float g_h[BATCH*DMEM];

// ---------------------------------------------------------------------------
// SGEMM: C[M,N] = A[M,K] * op(B) (+bias). 128x128x16 tiles, 8x8 microtile,
// double-buffered smem. mode: 0 plain; 1 causal tile skip; 2 K-limit (PV).
// ---------------------------------------------------------------------------
__global__ void __launch_bounds__(256, 2) sgemm128(
    const float* __restrict__ A, const float* __restrict__ B,
    const float* __restrict__ bias, float* __restrict__ C,
    int M, int N, int K,
    size_t sA, size_t sB, size_t sC,
    int transB, int mode)
{
    constexpr int BM = 128, BN = 128, BK = 16, PAD = 4;
    __shared__ float As[2][BK][BM + PAD];
    __shared__ float Bs[2][BK][BN + PAD];

    int bx = blockIdx.x, by = blockIdx.y, bz = blockIdx.z;
    int rowBase = by * BM, colBase = bx * BN;
    if (mode == 1 && rowBase + BM - 1 < colBase) return;
    int Kend = K;
    if (mode == 2) Kend = (rowBase + BM < K) ? rowBase + BM : K;

    const float* Ab = A + sA * (size_t)bz;
    const float* Bb = B + sB * (size_t)bz;
    float*       Cb = C + sC * (size_t)bz;

    int tid = threadIdx.x;
    int ty = tid >> 4, tx = tid & 15;
    int row0 = ty * 8;
    int c0 = tx * 4, c1 = 64 + tx * 4;

    int arow = tid >> 1, akof = (tid & 1) * 8;
    const float* aptr = Ab + (size_t)(rowBase + arow) * K + akof;

    int bkr = tid >> 4, bnc = (tid & 15) * 8;
    int bnr = tid >> 1, bkof = (tid & 1) * 8;
    const float* bptr = transB
        ? Bb + (size_t)(colBase + bnr) * K + bkof
        : Bb + (size_t)bkr * N + colBase + bnc;

    float acc[8][8];
#pragma unroll
    for (int i = 0; i < 8; i++)
#pragma unroll
        for (int j = 0; j < 8; j++) acc[i][j] = 0.0f;

    int nTiles = Kend / BK;

    {
        float4 a0 = *(const float4*)(aptr);
        float4 a1 = *(const float4*)(aptr + 4);
        As[0][akof + 0][arow] = a0.x; As[0][akof + 1][arow] = a0.y;
        As[0][akof + 2][arow] = a0.z; As[0][akof + 3][arow] = a0.w;
        As[0][akof + 4][arow] = a1.x; As[0][akof + 5][arow] = a1.y;
        As[0][akof + 6][arow] = a1.z; As[0][akof + 7][arow] = a1.w;
        float4 b0 = *(const float4*)(bptr);
        float4 b1 = *(const float4*)(bptr + 4);
        if (!transB) {
            *(float4*)&Bs[0][bkr][bnc]     = b0;
            *(float4*)&Bs[0][bkr][bnc + 4] = b1;
        } else {
            Bs[0][bkof + 0][bnr] = b0.x; Bs[0][bkof + 1][bnr] = b0.y;
            Bs[0][bkof + 2][bnr] = b0.z; Bs[0][bkof + 3][bnr] = b0.w;
            Bs[0][bkof + 4][bnr] = b1.x; Bs[0][bkof + 5][bnr] = b1.y;
            Bs[0][bkof + 6][bnr] = b1.z; Bs[0][bkof + 7][bnr] = b1.w;
        }
    }
    __syncthreads();

    int buf = 0;
    for (int t0 = 0; t0 < nTiles; t0++) {
        float4 na0, na1, nb0, nb1;
        bool nxt = (t0 + 1 < nTiles);
        if (nxt) {
            const float* ap = aptr + (t0 + 1) * BK;
            na0 = *(const float4*)(ap);
            na1 = *(const float4*)(ap + 4);
            const float* bp = transB ? bptr + (t0 + 1) * BK
                                     : bptr + (size_t)(t0 + 1) * BK * N;
            nb0 = *(const float4*)(bp);
            nb1 = *(const float4*)(bp + 4);
        }

#pragma unroll
        for (int kk = 0; kk < BK; kk++) {
            float4 a0 = *(const float4*)&As[buf][kk][row0];
            float4 a1 = *(const float4*)&As[buf][kk][row0 + 4];
            float4 b0 = *(const float4*)&Bs[buf][kk][c0];
            float4 b1 = *(const float4*)&Bs[buf][kk][c1];
            float a[8] = {a0.x, a0.y, a0.z, a0.w, a1.x, a1.y, a1.z, a1.w};
            float b[8] = {b0.x, b0.y, b0.z, b0.w, b1.x, b1.y, b1.z, b1.w};
#pragma unroll
            for (int i = 0; i < 8; i++)
#pragma unroll
                for (int j = 0; j < 8; j++)
                    acc[i][j] = fmaf(a[i], b[j], acc[i][j]);
        }

        if (nxt) {
            int nb = buf ^ 1;
            As[nb][akof + 0][arow] = na0.x; As[nb][akof + 1][arow] = na0.y;
            As[nb][akof + 2][arow] = na0.z; As[nb][akof + 3][arow] = na0.w;
            As[nb][akof + 4][arow] = na1.x; As[nb][akof + 5][arow] = na1.y;
            As[nb][akof + 6][arow] = na1.z; As[nb][akof + 7][arow] = na1.w;
            if (!transB) {
                *(float4*)&Bs[nb][bkr][bnc]     = nb0;
                *(float4*)&Bs[nb][bkr][bnc + 4] = nb1;
            } else {
                Bs[nb][bkof + 0][bnr] = nb0.x; Bs[nb][bkof + 1][bnr] = nb0.y;
                Bs[nb][bkof + 2][bnr] = nb0.z; Bs[nb][bkof + 3][bnr] = nb0.w;
                Bs[nb][bkof + 4][bnr] = nb1.x; Bs[nb][bkof + 5][bnr] = nb1.y;
                Bs[nb][bkof + 6][bnr] = nb1.z; Bs[nb][bkof + 7][bnr] = nb1.w;
            }
        }
        __syncthreads();
        buf ^= 1;
    }

    float4 bv0 = make_float4(0.f, 0.f, 0.f, 0.f);
    float4 bv1 = bv0;
    if (bias) {
        bv0 = *(const float4*)(bias + colBase + c0);
        bv1 = *(const float4*)(bias + colBase + c1);
    }
#pragma unroll
    for (int i = 0; i < 8; i++) {
        size_t row = (size_t)(rowBase + row0 + i);
        float4 o0 = make_float4(acc[i][0] + bv0.x, acc[i][1] + bv0.y,
                                acc[i][2] + bv0.z, acc[i][3] + bv0.w);
        float4 o1 = make_float4(acc[i][4] + bv1.x, acc[i][5] + bv1.y,
                                acc[i][6] + bv1.z, acc[i][7] + bv1.w);
        *(float4*)(Cb + row * N + colBase + c0) = o0;
        *(float4*)(Cb + row * N + colBase + c1) = o1;
    }
}

// ---------------------------------------------------------------------------
// Causal row softmax, in place (single exp pass, smem cache).
// ---------------------------------------------------------------------------
__global__ void softmax_causal_kernel()
{
    int r = blockIdx.x, b = blockIdx.y;
    float* row = g_S + ((size_t)b * SEQ + r) * SEQ;
    int len = r + 1;
    int tid = threadIdx.x;
    __shared__ float buf[SEQ];
    __shared__ float red[256];
    const float inv = rsqrtf(512.0f);

    float m = -3.4e38f;
    for (int i = tid; i < len; i += 256) m = fmaxf(m, row[i]);
    red[tid] = m; __syncthreads();
    for (int s = 128; s; s >>= 1) { if (tid < s) red[tid] = fmaxf(red[tid], red[tid + s]); __syncthreads(); }
    m = red[0] * inv;
    __syncthreads();

    float ssum = 0.0f;
    for (int i = tid; i < len; i += 256) {
        float e = __expf(row[i] * inv - m);
        buf[i] = e;
        ssum += e;
    }
    red[tid] = ssum; __syncthreads();
    for (int s = 128; s; s >>= 1) { if (tid < s) red[tid] += red[tid + s]; __syncthreads(); }
    float denom = 1.0f / red[0];
    __syncthreads();

    for (int i = tid; i < SEQ; i += 256)
        row[i] = (i < len) ? buf[i] * denom : 0.0f;
}

// ---------------------------------------------------------------------------
// Prefix pooling + h0.
// ---------------------------------------------------------------------------
__global__ void pool_kernel(const float* __restrict__ Wscore,
                            const float* __restrict__ Wp2h,
                            const float* __restrict__ bp2h)
{
    int b = blockIdx.x;
    const float* feat = g_feat + (size_t)b * SEQ * DPROJ;
    __shared__ float wsc[512];
    __shared__ float sc[512];
    __shared__ float pooled[512];
    __shared__ float red[256];
    int tid = threadIdx.x;

    for (int i = tid; i < 512; i += 256) wsc[i] = Wscore[i];
    __syncthreads();

    int w = tid >> 5, l = tid & 31;
    for (int u = w; u < ASSIST; u += 8) {
        float s = 0.0f;
        for (int p = l; p < DPROJ; p += 32)
            s = fmaf(feat[(size_t)u * DPROJ + p], wsc[p], s);
#pragma unroll
        for (int o = 16; o; o >>= 1) s += __shfl_xor_sync(0xffffffffu, s, o);
        if (l == 0) sc[u] = s;
    }
    __syncthreads();

    float m = fmaxf(sc[tid], sc[tid + 256]);
    red[tid] = m; __syncthreads();
    for (int s = 128; s; s >>= 1) { if (tid < s) red[tid] = fmaxf(red[tid], red[tid + s]); __syncthreads(); }
    m = red[0]; __syncthreads();

    float e0 = expf(sc[tid] - m), e1 = expf(sc[tid + 256] - m);
    red[tid] = e0 + e1; __syncthreads();
    for (int s = 128; s; s >>= 1) { if (tid < s) red[tid] += red[tid + s]; __syncthreads(); }
    float inv = 1.0f / red[0];
    __syncthreads();
    sc[tid] = e0 * inv; sc[tid + 256] = e1 * inv;
    __syncthreads();

    for (int p = tid; p < DPROJ; p += 256) {
        float acc = 0.0f;
        for (int u = 0; u < ASSIST; u++)
            acc = fmaf(sc[u], feat[(size_t)u * DPROJ + p], acc);
        pooled[p] = acc;
    }
    __syncthreads();

    for (int c = tid; c < DMEM; c += 256) {
        float acc = bp2h[c];
        for (int k = 0; k < DPROJ; k++)
            acc = fmaf(pooled[k], Wp2h[(size_t)k * DMEM + c], acc);
        g_h[b * DMEM + c] = tanhf(acc);
    }
}

__global__ void init_out_kernel(float* __restrict__ out, const float* __restrict__ bmem)
{
    int i = blockIdx.x * blockDim.x + threadIdx.x;
    if (i < BATCH * RUN) out[i] = bmem[0];
}

// ---------------------------------------------------------------------------
// Cluster-based sequential scan.
// Grid = 32 CTAs as 2 clusters of 16.  Cluster = 2 batches; CTA (rank R) owns
// cols [32R, 32R+32).  512 threads: c = tid&31 (col), seg = tid>>5 (16 k-segs
// of 32).  Uz/Ur register-resident (64 regs), Uh in smem.  h and r*h live in
// smem, replicated per CTA, exchanged by DSMEM broadcast stores + 2x
// cluster.sync per step.  No global sync, no persistent state -> replay-safe.
// ---------------------------------------------------------------------------
#define SCAN_THREADS 512
#define CL 16

// dynamic smem layout (bytes)
#define UH_OFF   0                 // float[512][32]   (uh[k*32+c])     65536
#define H_OFF    65536             // float[2][512]                      4096
#define RH_OFF   69632             // float[2][512]                      4096
#define PART_OFF 73728             // float[512][4]                      8192
#define ZS_OFF   81920             // float[2][32]                        256
#define WM_OFF   82176             // float[32]                           128
#define SCAN_SMEM 82432

__device__ __forceinline__ uint32_t smem_u32(const void* p) {
    uint32_t a;
    asm("{ .reg .u64 t; cvta.to.shared.u64 t, %1; cvt.u32.u64 %0, t; }"
        : "=r"(a) : "l"(p));
    return a;
}
__device__ __forceinline__ uint32_t mapa_rank(uint32_t saddr, uint32_t rank) {
    uint32_t r;
    asm("mapa.shared::cluster.u32 %0, %1, %2;" : "=r"(r) : "r"(saddr), "r"(rank));
    return r;
}
__device__ __forceinline__ void stc_f32(uint32_t addr, float v) {
    asm volatile("st.shared::cluster.f32 [%0], %1;" :: "r"(addr), "f"(v));
}
#define CLUSTER_SYNC() do { \
    asm volatile("barrier.cluster.arrive.aligned;" ::: "memory"); \
    asm volatile("barrier.cluster.wait.aligned;" ::: "memory"); \
} while (0)

__global__ void __launch_bounds__(SCAN_THREADS, 1) scan_cluster(
    const float* __restrict__ Uz, const float* __restrict__ Ur,
    const float* __restrict__ Uh, const float* __restrict__ Wmem,
    const float* __restrict__ Gz, const float* __restrict__ Gr,
    const float* __restrict__ Gh, float* __restrict__ out)
{
    extern __shared__ char smem[];
    float* uh_s = (float*)(smem + UH_OFF);     // [512][32]  uh_s[k*32+c]
    float* h_s  = (float*)(smem + H_OFF);      // [2][512]
    float* rh_s = (float*)(smem + RH_OFF);     // [2][512]
    float* part = (float*)(smem + PART_OFF);   // [512][4]
    float* z_s  = (float*)(smem + ZS_OFF);     // [2][32]
    float* wm_s = (float*)(smem + WM_OFF);     // [32]

    int tid = threadIdx.x;
    int c   = tid & 31;
    int seg = tid >> 5;            // warp id; all lanes of a warp share seg
    int kbase = seg * 32;

    uint32_t rank;
    asm("mov.u32 %0, %%cluster_ctarank;" : "=r"(rank));
    int cg0 = (int)rank * 32;
    int gb0 = (blockIdx.x >> 4) << 1;          // first batch of this cluster

    // register-resident Uz/Ur slices (col cg0+c, k in [kbase, kbase+32))
    float uz[32], ur[32];
#pragma unroll
    for (int i = 0; i < 32; i++) {
        uz[i] = Uz[(size_t)(kbase + i) * DMEM + cg0 + c];
        ur[i] = Ur[(size_t)(kbase + i) * DMEM + cg0 + c];
    }
    // Uh slice into smem: uh_s[k*32+c] = Uh[k][cg0+c]
    for (int idx = tid; idx < 512 * 32; idx += SCAN_THREADS) {
        int k = idx >> 5, cc = idx & 31;
        uh_s[idx] = __ldg(&Uh[(size_t)k * DMEM + cg0 + cc]);
    }
    if (tid < 32) wm_s[tid] = Wmem[cg0 + tid];

    // initial h (full 512 cols, both batches) from global
    h_s[tid]       = __ldcg(&g_h[(size_t)gb0 * DMEM + tid]);
    h_s[512 + tid] = __ldcg(&g_h[(size_t)(gb0 + 1) * DMEM + tid]);
    __syncthreads();

    uint32_t rh_base = smem_u32(rh_s);
    uint32_t h_base  = smem_u32(h_s);

    const float dtc = 1.0f / 1535.0f;

    for (int t = 0; t < RUN; t++) {
        float dtv = (t == 0) ? 0.0f : dtc;

        // prefetch streamed inputs for reducers
        float gA = 0.0f, gH = 0.0f;
        if (tid < 128) {
            int cc = tid & 31, b = (tid >> 5) & 1, mat = tid >> 6;
            const float* P = mat ? Gr : Gz;
            gA = __ldg(&P[((size_t)((gb0 + b) * RUN + t)) * DMEM + cg0 + cc]);
        }
        if (tid < 64) {
            int cc = tid & 31, b = tid >> 5;
            gH = __ldg(&Gh[((size_t)((gb0 + b) * RUN + t)) * DMEM + cg0 + cc]);
        }

        // ---- phase A: z/r partial dots (h broadcast-LDS, vectorized) ----
        float pz0 = 0.f, pz1 = 0.f, pr0 = 0.f, pr1 = 0.f;
        const float4* h0p = (const float4*)&h_s[kbase];
        const float4* h1p = (const float4*)&h_s[512 + kbase];
#pragma unroll
        for (int i = 0; i < 8; i++) {
            float4 h0 = h0p[i], h1 = h1p[i];
            pz0 = fmaf(h0.x, uz[4*i+0], pz0); pz1 = fmaf(h1.x, uz[4*i+0], pz1);
            pr0 = fmaf(h0.x, ur[4*i+0], pr0); pr1 = fmaf(h1.x, ur[4*i+0], pr1);
            pz0 = fmaf(h0.y, uz[4*i+1], pz0); pz1 = fmaf(h1.y, uz[4*i+1], pz1);
            pr0 = fmaf(h0.y, ur[4*i+1], pr0); pr1 = fmaf(h1.y, ur[4*i+1], pr1);
            pz0 = fmaf(h0.z, uz[4*i+2], pz0); pz1 = fmaf(h1.z, uz[4*i+2], pz1);
            pr0 = fmaf(h0.z, ur[4*i+2], pr0); pr1 = fmaf(h1.z, ur[4*i+2], pr1);
            pz0 = fmaf(h0.w, uz[4*i+3], pz0); pz1 = fmaf(h1.w, uz[4*i+3], pz1);
            pr0 = fmaf(h0.w, ur[4*i+3], pr0); pr1 = fmaf(h1.w, ur[4*i+3], pr1);
        }
        ((float4*)part)[tid] = make_float4(pz0, pz1, pr0, pr1);
        __syncthreads();

        if (tid < 128) {
            int cc = tid & 31, b = (tid >> 5) & 1, mat = tid >> 6;
            int slot = mat * 2 + b;
            float s = 0.0f;
#pragma unroll
            for (int sg = 0; sg < 16; sg++)
                s += part[(sg * 32 + cc) * 4 + slot];
            float v = gA + s;
            float sig = 1.0f / (1.0f + expf(-v));
            if (mat == 0) {
                z_s[b * 32 + cc] = sig;
            } else {
                float rhv = sig * h_s[b * 512 + cg0 + cc];
                uint32_t a = rh_base + (uint32_t)((b << 9) + cg0 + cc) * 4u;
#pragma unroll
                for (int rk = 0; rk < CL; rk++)
                    stc_f32(mapa_rank(a, (uint32_t)rk), rhv);
            }
        }
        CLUSTER_SYNC();

        // ---- phase B: candidate partial dots ----
        float ph0 = 0.f, ph1 = 0.f;
        const float4* r0p = (const float4*)&rh_s[kbase];
        const float4* r1p = (const float4*)&rh_s[512 + kbase];
#pragma unroll
        for (int i = 0; i < 8; i++) {
            float4 r0 = r0p[i], r1 = r1p[i];
            int k4 = (kbase + 4 * i) * 32 + c;
            float u0 = uh_s[k4];
            float u1 = uh_s[k4 + 32];
            float u2 = uh_s[k4 + 64];
            float u3 = uh_s[k4 + 96];
            ph0 = fmaf(r0.x, u0, ph0); ph1 = fmaf(r1.x, u0, ph1);
            ph0 = fmaf(r0.y, u1, ph0); ph1 = fmaf(r1.y, u1, ph1);
            ph0 = fmaf(r0.z, u2, ph0); ph1 = fmaf(r1.z, u2, ph1);
            ph0 = fmaf(r0.w, u3, ph0); ph1 = fmaf(r1.w, u3, ph1);
        }
        *(float2*)&part[tid * 4] = make_float2(ph0, ph1);
        __syncthreads();

        if (tid < 64) {
            int cc = tid & 31, b = tid >> 5;
            float s = 0.0f;
#pragma unroll
            for (int sg = 0; sg < 16; sg++)
                s += part[(sg * 32 + cc) * 4 + b];
            float hh   = tanhf(gH + s);
            int   cg   = cg0 + cc;
            float hold = h_s[b * 512 + cg];
            float zv   = z_s[b * 32 + cc];
            float hnew = hold + zv * (hh - hold);
            float hout = hnew + dtv * (hnew - hold);
            uint32_t a = h_base + (uint32_t)((b << 9) + cg) * 4u;
#pragma unroll
            for (int rk = 0; rk < CL; rk++)
                stc_f32(mapa_rank(a, (uint32_t)rk), hout);
            // partial logit over this CTA's 32 cols (full warp per batch)
            float lv = hout * wm_s[cc];
#pragma unroll
            for (int o = 16; o; o >>= 1)
                lv += __shfl_xor_sync(0xffffffffu, lv, o);
            if (cc == 0)
                atomicAdd(&out[(gb0 + b) * RUN + t], lv);
        }
        CLUSTER_SYNC();
    }
}

// ---------------------------------------------------------------------------
// Host
// ---------------------------------------------------------------------------
extern "C" void kernel_launch(void* const* d_in, const int* in_sizes, int n_in,
                              void* d_out, int out_size)
{
    const float* x      = (const float*)d_in[0];
    const float* Wq     = (const float*)d_in[1];
    const float* bq     = (const float*)d_in[2];
    const float* Wk     = (const float*)d_in[3];
    const float* bk     = (const float*)d_in[4];
    const float* Wv     = (const float*)d_in[5];
    const float* bv     = (const float*)d_in[6];
    const float* Wz     = (const float*)d_in[7];
    const float* Uz     = (const float*)d_in[8];
    const float* bz     = (const float*)d_in[9];
    const float* Wr     = (const float*)d_in[10];
    const float* Ur     = (const float*)d_in[11];
    const float* br     = (const float*)d_in[12];
    const float* Wh     = (const float*)d_in[13];
    const float* Uh     = (const float*)d_in[14];
    const float* bh     = (const float*)d_in[15];
    const float* Wmem   = (const float*)d_in[16];
    const float* bmem   = (const float*)d_in[17];
    const float* Wp2h   = (const float*)d_in[18];
    const float* bp2h   = (const float*)d_in[19];
    const float* Wscore = (const float*)d_in[20];
    (void)in_sizes; (void)n_in;
    float* out = (float*)d_out;

    float *pQ, *pK, *pV, *pS, *pF, *pGz, *pGr, *pGh;
    cudaGetSymbolAddress((void**)&pQ,  g_Q);
    cudaGetSymbolAddress((void**)&pK,  g_K);
    cudaGetSymbolAddress((void**)&pV,  g_V);
    cudaGetSymbolAddress((void**)&pS,  g_S);
    cudaGetSymbolAddress((void**)&pF,  g_feat);
    cudaGetSymbolAddress((void**)&pGz, g_Gz);
    cudaGetSymbolAddress((void**)&pGr, g_Gr);
    cudaGetSymbolAddress((void**)&pGh, g_Gh);

    dim3 t256(256);

    // QKV projections
    {
        dim3 g(DPROJ / 128, ROWS / 128, 1);
        sgemm128<<<g, t256>>>(x, Wq, bq, pQ, ROWS, DPROJ, DIN, 0, 0, 0, 0, 0);
        sgemm128<<<g, t256>>>(x, Wk, bk, pK, ROWS, DPROJ, DIN, 0, 0, 0, 0, 0);
        sgemm128<<<g, t256>>>(x, Wv, bv, pV, ROWS, DPROJ, DIN, 0, 0, 0, 0, 0);
    }

    // scores = Q K^T (causal tile skip)
    {
        dim3 g(SEQ / 128, SEQ / 128, BATCH);
        sgemm128<<<g, t256>>>(pQ, pK, nullptr, pS, SEQ, SEQ, DPROJ,
                              (size_t)SEQ * DPROJ, (size_t)SEQ * DPROJ,
                              (size_t)SEQ * SEQ, 1, 1);
    }

    softmax_causal_kernel<<<dim3(SEQ, BATCH), t256>>>();

    // feat = P V (K-limited: P lower-triangular)
    {
        dim3 g(DPROJ / 128, SEQ / 128, BATCH);
        sgemm128<<<g, t256>>>(pS, pV, nullptr, pF, SEQ, DPROJ, SEQ,
                              (size_t)SEQ * SEQ, (size_t)SEQ * DPROJ,
                              (size_t)SEQ * DPROJ, 0, 2);
    }

    pool_kernel<<<BATCH, t256>>>(Wscore, Wp2h, bp2h);

    // G* = feat_assist @ W* + b*
    {
        dim3 g(DMEM / 128, RUN / 128, BATCH);
        const float* Aoff = pF + (size_t)ASSIST * DPROJ;
        sgemm128<<<g, t256>>>(Aoff, Wz, bz, pGz, RUN, DMEM, DPROJ,
                              (size_t)SEQ * DPROJ, 0, (size_t)RUN * DMEM, 0, 0);
        sgemm128<<<g, t256>>>(Aoff, Wr, br, pGr, RUN, DMEM, DPROJ,
                              (size_t)SEQ * DPROJ, 0, (size_t)RUN * DMEM, 0, 0);
        sgemm128<<<g, t256>>>(Aoff, Wh, bh, pGh, RUN, DMEM, DPROJ,
                              (size_t)SEQ * DPROJ, 0, (size_t)RUN * DMEM, 0, 0);
    }

    init_out_kernel<<<(BATCH * RUN + 255) / 256, t256>>>(out, bmem);

    // cluster scan: 2 clusters x 16 CTAs x 512 threads
    cudaFuncSetAttribute(scan_cluster,
                         cudaFuncAttributeMaxDynamicSharedMemorySize, SCAN_SMEM);
    cudaFuncSetAttribute(scan_cluster,
                         cudaFuncAttributeNonPortableClusterSizeAllowed, 1);
    {
        cudaLaunchConfig_t cfg = {};
        cfg.gridDim  = dim3(32, 1, 1);
        cfg.blockDim = dim3(SCAN_THREADS, 1, 1);
        cfg.dynamicSmemBytes = SCAN_SMEM;
        cfg.stream = 0;
        cudaLaunchAttribute attrs[1];
        attrs[0].id = cudaLaunchAttributeClusterDimension;
        attrs[0].val.clusterDim.x = CL;
        attrs[0].val.clusterDim.y = 1;
        attrs[0].val.clusterDim.z = 1;
        cfg.attrs = attrs;
        cfg.numAttrs = 1;
        cudaLaunchKernelEx(&cfg, scan_cluster,
                           Uz, Ur, Uh, Wmem,
                           (const float*)pGz, (const float*)pGr,
                           (const float*)pGh, out);
    }

    (void)out_size;
}

// round 6
// speedup vs baseline: 2.2879x; 1.1370x over previous
#include <cuda_runtime.h>
#include <cuda_bf16.h>
#include <math.h>
#include <stdint.h>

// ---------------------------------------------------------------------------
// Problem constants
// ---------------------------------------------------------------------------
#define BATCH   4
#define SEQ     2048
#define DIN     4096
#define DPROJ   512
#define DMEM    512
#define ASSIST  512
#define RUN     1536
#define ROWS    (BATCH*SEQ)   // 8192

// ---------------------------------------------------------------------------
// Device scratch
// ---------------------------------------------------------------------------
__device__ float g_Q[(size_t)ROWS*DPROJ];
__device__ float g_K[(size_t)ROWS*DPROJ];
__device__ float g_V[(size_t)ROWS*DPROJ];
__device__ float g_S[(size_t)BATCH*SEQ*SEQ];
__device__ float g_feat[(size_t)ROWS*DPROJ];
__device__ float g_Gz[(size_t)BATCH*RUN*DMEM];
__device__ float g_Gr[(size_t)BATCH*RUN*DMEM];
__device__ float g_Gh[(size_t)BATCH*RUN*DMEM];
__device__ float g_h[BATCH*DMEM];

// ---------------------------------------------------------------------------
// SGEMM: C[M,N] = A[M,K] * op(B) (+bias). 128x128x16 tiles, 8x8 microtile,
// double-buffered smem. mode: 0 plain; 1 causal tile skip; 2 K-limit (PV).
// ---------------------------------------------------------------------------
__global__ void __launch_bounds__(256, 2) sgemm128(
    const float* __restrict__ A, const float* __restrict__ B,
    const float* __restrict__ bias, float* __restrict__ C,
    int M, int N, int K,
    size_t sA, size_t sB, size_t sC,
    int transB, int mode)
{
    constexpr int BM = 128, BN = 128, BK = 16, PAD = 4;
    __shared__ float As[2][BK][BM + PAD];
    __shared__ float Bs[2][BK][BN + PAD];

    int bx = blockIdx.x, by = blockIdx.y, bz = blockIdx.z;
    int rowBase = by * BM, colBase = bx * BN;
    if (mode == 1 && rowBase + BM - 1 < colBase) return;
    int Kend = K;
    if (mode == 2) Kend = (rowBase + BM < K) ? rowBase + BM : K;

    const float* Ab = A + sA * (size_t)bz;
    const float* Bb = B + sB * (size_t)bz;
    float*       Cb = C + sC * (size_t)bz;

    int tid = threadIdx.x;
    int ty = tid >> 4, tx = tid & 15;
    int row0 = ty * 8;
    int c0 = tx * 4, c1 = 64 + tx * 4;

    int arow = tid >> 1, akof = (tid & 1) * 8;
    const float* aptr = Ab + (size_t)(rowBase + arow) * K + akof;

    int bkr = tid >> 4, bnc = (tid & 15) * 8;
    int bnr = tid >> 1, bkof = (tid & 1) * 8;
    const float* bptr = transB
        ? Bb + (size_t)(colBase + bnr) * K + bkof
        : Bb + (size_t)bkr * N + colBase + bnc;

    float acc[8][8];
#pragma unroll
    for (int i = 0; i < 8; i++)
#pragma unroll
        for (int j = 0; j < 8; j++) acc[i][j] = 0.0f;

    int nTiles = Kend / BK;

    {
        float4 a0 = *(const float4*)(aptr);
        float4 a1 = *(const float4*)(aptr + 4);
        As[0][akof + 0][arow] = a0.x; As[0][akof + 1][arow] = a0.y;
        As[0][akof + 2][arow] = a0.z; As[0][akof + 3][arow] = a0.w;
        As[0][akof + 4][arow] = a1.x; As[0][akof + 5][arow] = a1.y;
        As[0][akof + 6][arow] = a1.z; As[0][akof + 7][arow] = a1.w;
        float4 b0 = *(const float4*)(bptr);
        float4 b1 = *(const float4*)(bptr + 4);
        if (!transB) {
            *(float4*)&Bs[0][bkr][bnc]     = b0;
            *(float4*)&Bs[0][bkr][bnc + 4] = b1;
        } else {
            Bs[0][bkof + 0][bnr] = b0.x; Bs[0][bkof + 1][bnr] = b0.y;
            Bs[0][bkof + 2][bnr] = b0.z; Bs[0][bkof + 3][bnr] = b0.w;
            Bs[0][bkof + 4][bnr] = b1.x; Bs[0][bkof + 5][bnr] = b1.y;
            Bs[0][bkof + 6][bnr] = b1.z; Bs[0][bkof + 7][bnr] = b1.w;
        }
    }
    __syncthreads();

    int buf = 0;
    for (int t0 = 0; t0 < nTiles; t0++) {
        float4 na0, na1, nb0, nb1;
        bool nxt = (t0 + 1 < nTiles);
        if (nxt) {
            const float* ap = aptr + (t0 + 1) * BK;
            na0 = *(const float4*)(ap);
            na1 = *(const float4*)(ap + 4);
            const float* bp = transB ? bptr + (t0 + 1) * BK
                                     : bptr + (size_t)(t0 + 1) * BK * N;
            nb0 = *(const float4*)(bp);
            nb1 = *(const float4*)(bp + 4);
        }

#pragma unroll
        for (int kk = 0; kk < BK; kk++) {
            float4 a0 = *(const float4*)&As[buf][kk][row0];
            float4 a1 = *(const float4*)&As[buf][kk][row0 + 4];
            float4 b0 = *(const float4*)&Bs[buf][kk][c0];
            float4 b1 = *(const float4*)&Bs[buf][kk][c1];
            float a[8] = {a0.x, a0.y, a0.z, a0.w, a1.x, a1.y, a1.z, a1.w};
            float b[8] = {b0.x, b0.y, b0.z, b0.w, b1.x, b1.y, b1.z, b1.w};
#pragma unroll
            for (int i = 0; i < 8; i++)
#pragma unroll
                for (int j = 0; j < 8; j++)
                    acc[i][j] = fmaf(a[i], b[j], acc[i][j]);
        }

        if (nxt) {
            int nb = buf ^ 1;
            As[nb][akof + 0][arow] = na0.x; As[nb][akof + 1][arow] = na0.y;
            As[nb][akof + 2][arow] = na0.z; As[nb][akof + 3][arow] = na0.w;
            As[nb][akof + 4][arow] = na1.x; As[nb][akof + 5][arow] = na1.y;
            As[nb][akof + 6][arow] = na1.z; As[nb][akof + 7][arow] = na1.w;
            if (!transB) {
                *(float4*)&Bs[nb][bkr][bnc]     = nb0;
                *(float4*)&Bs[nb][bkr][bnc + 4] = nb1;
            } else {
                Bs[nb][bkof + 0][bnr] = nb0.x; Bs[nb][bkof + 1][bnr] = nb0.y;
                Bs[nb][bkof + 2][bnr] = nb0.z; Bs[nb][bkof + 3][bnr] = nb0.w;
                Bs[nb][bkof + 4][bnr] = nb1.x; Bs[nb][bkof + 5][bnr] = nb1.y;
                Bs[nb][bkof + 6][bnr] = nb1.z; Bs[nb][bkof + 7][bnr] = nb1.w;
            }
        }
        __syncthreads();
        buf ^= 1;
    }

    float4 bv0 = make_float4(0.f, 0.f, 0.f, 0.f);
    float4 bv1 = bv0;
    if (bias) {
        bv0 = *(const float4*)(bias + colBase + c0);
        bv1 = *(const float4*)(bias + colBase + c1);
    }
#pragma unroll
    for (int i = 0; i < 8; i++) {
        size_t row = (size_t)(rowBase + row0 + i);
        float4 o0 = make_float4(acc[i][0] + bv0.x, acc[i][1] + bv0.y,
                                acc[i][2] + bv0.z, acc[i][3] + bv0.w);
        float4 o1 = make_float4(acc[i][4] + bv1.x, acc[i][5] + bv1.y,
                                acc[i][6] + bv1.z, acc[i][7] + bv1.w);
        *(float4*)(Cb + row * N + colBase + c0) = o0;
        *(float4*)(Cb + row * N + colBase + c1) = o1;
    }
}

// ---------------------------------------------------------------------------
// Causal row softmax, in place (single exp pass, smem cache).
// ---------------------------------------------------------------------------
__global__ void softmax_causal_kernel()
{
    int r = blockIdx.x, b = blockIdx.y;
    float* row = g_S + ((size_t)b * SEQ + r) * SEQ;
    int len = r + 1;
    int tid = threadIdx.x;
    __shared__ float buf[SEQ];
    __shared__ float red[256];
    const float inv = rsqrtf(512.0f);

    float m = -3.4e38f;
    for (int i = tid; i < len; i += 256) m = fmaxf(m, row[i]);
    red[tid] = m; __syncthreads();
    for (int s = 128; s; s >>= 1) { if (tid < s) red[tid] = fmaxf(red[tid], red[tid + s]); __syncthreads(); }
    m = red[0] * inv;
    __syncthreads();

    float ssum = 0.0f;
    for (int i = tid; i < len; i += 256) {
        float e = __expf(row[i] * inv - m);
        buf[i] = e;
        ssum += e;
    }
    red[tid] = ssum; __syncthreads();
    for (int s = 128; s; s >>= 1) { if (tid < s) red[tid] += red[tid + s]; __syncthreads(); }
    float denom = 1.0f / red[0];
    __syncthreads();

    for (int i = tid; i < SEQ; i += 256)
        row[i] = (i < len) ? buf[i] * denom : 0.0f;
}

// ---------------------------------------------------------------------------
// Prefix pooling + h0.
// ---------------------------------------------------------------------------
__global__ void pool_kernel(const float* __restrict__ Wscore,
                            const float* __restrict__ Wp2h,
                            const float* __restrict__ bp2h)
{
    int b = blockIdx.x;
    const float* feat = g_feat + (size_t)b * SEQ * DPROJ;
    __shared__ float wsc[512];
    __shared__ float sc[512];
    __shared__ float pooled[512];
    __shared__ float red[256];
    int tid = threadIdx.x;

    for (int i = tid; i < 512; i += 256) wsc[i] = Wscore[i];
    __syncthreads();

    int w = tid >> 5, l = tid & 31;
    for (int u = w; u < ASSIST; u += 8) {
        float s = 0.0f;
        for (int p = l; p < DPROJ; p += 32)
            s = fmaf(feat[(size_t)u * DPROJ + p], wsc[p], s);
#pragma unroll
        for (int o = 16; o; o >>= 1) s += __shfl_xor_sync(0xffffffffu, s, o);
        if (l == 0) sc[u] = s;
    }
    __syncthreads();

    float m = fmaxf(sc[tid], sc[tid + 256]);
    red[tid] = m; __syncthreads();
    for (int s = 128; s; s >>= 1) { if (tid < s) red[tid] = fmaxf(red[tid], red[tid + s]); __syncthreads(); }
    m = red[0]; __syncthreads();

    float e0 = expf(sc[tid] - m), e1 = expf(sc[tid + 256] - m);
    red[tid] = e0 + e1; __syncthreads();
    for (int s = 128; s; s >>= 1) { if (tid < s) red[tid] += red[tid + s]; __syncthreads(); }
    float inv = 1.0f / red[0];
    __syncthreads();
    sc[tid] = e0 * inv; sc[tid + 256] = e1 * inv;
    __syncthreads();

    for (int p = tid; p < DPROJ; p += 256) {
        float acc = 0.0f;
        for (int u = 0; u < ASSIST; u++)
            acc = fmaf(sc[u], feat[(size_t)u * DPROJ + p], acc);
        pooled[p] = acc;
    }
    __syncthreads();

    for (int c = tid; c < DMEM; c += 256) {
        float acc = bp2h[c];
        for (int k = 0; k < DPROJ; k++)
            acc = fmaf(pooled[k], Wp2h[(size_t)k * DMEM + c], acc);
        g_h[b * DMEM + c] = tanhf(acc);
    }
}

__global__ void init_out_kernel(float* __restrict__ out, const float* __restrict__ bmem)
{
    int i = blockIdx.x * blockDim.x + threadIdx.x;
    if (i < BATCH * RUN) out[i] = bmem[0];
}

// ---------------------------------------------------------------------------
// Cluster-based sequential scan — ONE BATCH PER CLUSTER.
// Grid = 64 CTAs as 4 clusters of 16 (64 SMs).  CTA rank R owns cols
// [32R, 32R+32).  512 threads: c = tid&31 (col), seg = tid>>5 (16 k-segs of
// 32).  Uz/Ur register-resident (64 regs), Uh in smem.  h / r*h replicated
// per CTA, exchanged by DSMEM broadcast stores + 2 cluster.syncs per step.
// z gate kept in a register (same thread computes and consumes it).
// ---------------------------------------------------------------------------
#define SCAN_THREADS 512
#define CL 16

// dynamic smem layout (bytes)
#define UH_OFF   0                 // float[512][32]  uh_s[k*32+c]     65536
#define H_OFF    65536             // float[512]                        2048
#define RH_OFF   67584             // float[512]                        2048
#define PART_OFF 69632             // float2[512]                       4096
#define WM_OFF   73728             // float[32]                          128
#define SCAN_SMEM 73856

__device__ __forceinline__ uint32_t smem_u32(const void* p) {
    uint32_t a;
    asm("{ .reg .u64 t; cvta.to.shared.u64 t, %1; cvt.u32.u64 %0, t; }"
        : "=r"(a) : "l"(p));
    return a;
}
__device__ __forceinline__ uint32_t mapa_rank(uint32_t saddr, uint32_t rank) {
    uint32_t r;
    asm("mapa.shared::cluster.u32 %0, %1, %2;" : "=r"(r) : "r"(saddr), "r"(rank));
    return r;
}
__device__ __forceinline__ void stc_f32(uint32_t addr, float v) {
    asm volatile("st.shared::cluster.f32 [%0], %1;" :: "r"(addr), "f"(v));
}
#define CLUSTER_SYNC() do { \
    asm volatile("barrier.cluster.arrive.aligned;" ::: "memory"); \
    asm volatile("barrier.cluster.wait.aligned;" ::: "memory"); \
} while (0)

__global__ void __launch_bounds__(SCAN_THREADS, 1) scan_cluster(
    const float* __restrict__ Uz, const float* __restrict__ Ur,
    const float* __restrict__ Uh, const float* __restrict__ Wmem,
    const float* __restrict__ Gz, const float* __restrict__ Gr,
    const float* __restrict__ Gh, float* __restrict__ out)
{
    extern __shared__ char smem[];
    float*  uh_s = (float*)(smem + UH_OFF);    // [512][32]
    float*  h_s  = (float*)(smem + H_OFF);     // [512]
    float*  rh_s = (float*)(smem + RH_OFF);    // [512]
    float2* part = (float2*)(smem + PART_OFF); // [512]
    float*  wm_s = (float*)(smem + WM_OFF);    // [32]

    int tid = threadIdx.x;
    int c   = tid & 31;
    int seg = tid >> 5;            // warp id == k-segment
    int kbase = seg * 32;

    uint32_t rank;
    asm("mov.u32 %0, %%cluster_ctarank;" : "=r"(rank));
    int cg0 = (int)rank * 32;
    int gb  = blockIdx.x >> 4;     // batch = cluster id

    // register-resident Uz/Ur slices (col cg0+c, k in [kbase, kbase+32))
    float uz[32], ur[32];
#pragma unroll
    for (int i = 0; i < 32; i++) {
        uz[i] = Uz[(size_t)(kbase + i) * DMEM + cg0 + c];
        ur[i] = Ur[(size_t)(kbase + i) * DMEM + cg0 + c];
    }
    // Uh slice into smem: uh_s[k*32+cc] = Uh[k][cg0+cc]
    for (int idx = tid; idx < 512 * 32; idx += SCAN_THREADS) {
        int k = idx >> 5, cc = idx & 31;
        uh_s[idx] = __ldg(&Uh[(size_t)k * DMEM + cg0 + cc]);
    }
    if (tid < 32) wm_s[tid] = Wmem[cg0 + tid];

    // initial h (full 512 cols of this batch)
    h_s[tid] = __ldcg(&g_h[(size_t)gb * DMEM + tid]);
    __syncthreads();

    uint32_t rh_base = smem_u32(rh_s);
    uint32_t h_base  = smem_u32(h_s);

    const float dtc = 1.0f / 1535.0f;
    float zreg = 0.0f;             // z gate, lives in tid<32 threads

    for (int t = 0; t < RUN; t++) {
        float dtv = (t == 0) ? 0.0f : dtc;

        // prefetch streamed inputs for reducers
        float gA = 0.0f, gH = 0.0f;
        if (tid < 64) {
            int cc = tid & 31, mat = tid >> 5;
            const float* P = mat ? Gr : Gz;
            gA = __ldg(&P[((size_t)(gb * RUN + t)) * DMEM + cg0 + cc]);
        }
        if (tid < 32) {
            gH = __ldg(&Gh[((size_t)(gb * RUN + t)) * DMEM + cg0 + tid]);
        }

        // ---- phase A: z/r partial dots over this thread's 32-k slice ----
        float pz = 0.f, pr = 0.f;
        const float4* hp = (const float4*)&h_s[kbase];
#pragma unroll
        for (int i = 0; i < 8; i++) {
            float4 h4 = hp[i];
            pz = fmaf(h4.x, uz[4*i+0], pz); pr = fmaf(h4.x, ur[4*i+0], pr);
            pz = fmaf(h4.y, uz[4*i+1], pz); pr = fmaf(h4.y, ur[4*i+1], pr);
            pz = fmaf(h4.z, uz[4*i+2], pz); pr = fmaf(h4.z, ur[4*i+2], pr);
            pz = fmaf(h4.w, uz[4*i+3], pz); pr = fmaf(h4.w, ur[4*i+3], pr);
        }
        part[tid] = make_float2(pz, pr);
        __syncthreads();

        if (tid < 64) {
            int cc = tid & 31, mat = tid >> 5;
            float s = 0.0f;
#pragma unroll
            for (int sg = 0; sg < 16; sg++) {
                float2 p = part[sg * 32 + cc];
                s += mat ? p.y : p.x;
            }
            float v = gA + s;
            float sig = 1.0f / (1.0f + expf(-v));
            if (mat == 0) {
                zreg = sig;                     // consumed by same thread in B
            } else {
                float rhv = sig * h_s[cg0 + cc];
                uint32_t a = rh_base + (uint32_t)(cg0 + cc) * 4u;
#pragma unroll
                for (int rk = 0; rk < CL; rk++)
                    stc_f32(mapa_rank(a, (uint32_t)rk), rhv);
            }
        }
        CLUSTER_SYNC();

        // ---- phase B: candidate partial dots ----
        float ph = 0.f;
        const float4* rp = (const float4*)&rh_s[kbase];
#pragma unroll
        for (int i = 0; i < 8; i++) {
            float4 r4 = rp[i];
            int k4 = (kbase + 4 * i) * 32 + c;
            ph = fmaf(r4.x, uh_s[k4],      ph);
            ph = fmaf(r4.y, uh_s[k4 + 32], ph);
            ph = fmaf(r4.z, uh_s[k4 + 64], ph);
            ph = fmaf(r4.w, uh_s[k4 + 96], ph);
        }
        part[tid].x = ph;
        __syncthreads();

        if (tid < 32) {                          // one full warp, cc = tid
            int cc = tid;
            float s = 0.0f;
#pragma unroll
            for (int sg = 0; sg < 16; sg++)
                s += part[sg * 32 + cc].x;
            float hh   = tanhf(gH + s);
            int   cg   = cg0 + cc;
            float hold = h_s[cg];
            float hnew = hold + zreg * (hh - hold);
            float hout = hnew + dtv * (hnew - hold);
            uint32_t a = h_base + (uint32_t)cg * 4u;
#pragma unroll
            for (int rk = 0; rk < CL; rk++)
                stc_f32(mapa_rank(a, (uint32_t)rk), hout);
            // partial logit over this CTA's 32 cols
            float lv = hout * wm_s[cc];
#pragma unroll
            for (int o = 16; o; o >>= 1)
                lv += __shfl_xor_sync(0xffffffffu, lv, o);
            if (cc == 0)
                atomicAdd(&out[gb * RUN + t], lv);
        }
        CLUSTER_SYNC();
    }
}

// ---------------------------------------------------------------------------
// Host
// ---------------------------------------------------------------------------
extern "C" void kernel_launch(void* const* d_in, const int* in_sizes, int n_in,
                              void* d_out, int out_size)
{
    const float* x      = (const float*)d_in[0];
    const float* Wq     = (const float*)d_in[1];
    const float* bq     = (const float*)d_in[2];
    const float* Wk     = (const float*)d_in[3];
    const float* bk     = (const float*)d_in[4];
    const float* Wv     = (const float*)d_in[5];
    const float* bv     = (const float*)d_in[6];
    const float* Wz     = (const float*)d_in[7];
    const float* Uz     = (const float*)d_in[8];
    const float* bz     = (const float*)d_in[9];
    const float* Wr     = (const float*)d_in[10];
    const float* Ur     = (const float*)d_in[11];
    const float* br     = (const float*)d_in[12];
    const float* Wh     = (const float*)d_in[13];
    const float* Uh     = (const float*)d_in[14];
    const float* bh     = (const float*)d_in[15];
    const float* Wmem   = (const float*)d_in[16];
    const float* bmem   = (const float*)d_in[17];
    const float* Wp2h   = (const float*)d_in[18];
    const float* bp2h   = (const float*)d_in[19];
    const float* Wscore = (const float*)d_in[20];
    (void)in_sizes; (void)n_in;
    float* out = (float*)d_out;

    float *pQ, *pK, *pV, *pS, *pF, *pGz, *pGr, *pGh;
    cudaGetSymbolAddress((void**)&pQ,  g_Q);
    cudaGetSymbolAddress((void**)&pK,  g_K);
    cudaGetSymbolAddress((void**)&pV,  g_V);
    cudaGetSymbolAddress((void**)&pS,  g_S);
    cudaGetSymbolAddress((void**)&pF,  g_feat);
    cudaGetSymbolAddress((void**)&pGz, g_Gz);
    cudaGetSymbolAddress((void**)&pGr, g_Gr);
    cudaGetSymbolAddress((void**)&pGh, g_Gh);

    dim3 t256(256);

    // QKV projections
    {
        dim3 g(DPROJ / 128, ROWS / 128, 1);
        sgemm128<<<g, t256>>>(x, Wq, bq, pQ, ROWS, DPROJ, DIN, 0, 0, 0, 0, 0);
        sgemm128<<<g, t256>>>(x, Wk, bk, pK, ROWS, DPROJ, DIN, 0, 0, 0, 0, 0);
        sgemm128<<<g, t256>>>(x, Wv, bv, pV, ROWS, DPROJ, DIN, 0, 0, 0, 0, 0);
    }

    // scores = Q K^T (causal tile skip)
    {
        dim3 g(SEQ / 128, SEQ / 128, BATCH);
        sgemm128<<<g, t256>>>(pQ, pK, nullptr, pS, SEQ, SEQ, DPROJ,
                              (size_t)SEQ * DPROJ, (size_t)SEQ * DPROJ,
                              (size_t)SEQ * SEQ, 1, 1);
    }

    softmax_causal_kernel<<<dim3(SEQ, BATCH), t256>>>();

    // feat = P V (K-limited: P lower-triangular)
    {
        dim3 g(DPROJ / 128, SEQ / 128, BATCH);
        sgemm128<<<g, t256>>>(pS, pV, nullptr, pF, SEQ, DPROJ, SEQ,
                              (size_t)SEQ * SEQ, (size_t)SEQ * DPROJ,
                              (size_t)SEQ * DPROJ, 0, 2);
    }

    pool_kernel<<<BATCH, t256>>>(Wscore, Wp2h, bp2h);

    // G* = feat_assist @ W* + b*
    {
        dim3 g(DMEM / 128, RUN / 128, BATCH);
        const float* Aoff = pF + (size_t)ASSIST * DPROJ;
        sgemm128<<<g, t256>>>(Aoff, Wz, bz, pGz, RUN, DMEM, DPROJ,
                              (size_t)SEQ * DPROJ, 0, (size_t)RUN * DMEM, 0, 0);
        sgemm128<<<g, t256>>>(Aoff, Wr, br, pGr, RUN, DMEM, DPROJ,
                              (size_t)SEQ * DPROJ, 0, (size_t)RUN * DMEM, 0, 0);
        sgemm128<<<g, t256>>>(Aoff, Wh, bh, pGh, RUN, DMEM, DPROJ,
                              (size_t)SEQ * DPROJ, 0, (size_t)RUN * DMEM, 0, 0);
    }

    init_out_kernel<<<(BATCH * RUN + 255) / 256, t256>>>(out, bmem);

    // cluster scan: 4 clusters x 16 CTAs x 512 threads (1 batch / cluster)
    cudaFuncSetAttribute(scan_cluster,
                         cudaFuncAttributeMaxDynamicSharedMemorySize, SCAN_SMEM);
    cudaFuncSetAttribute(scan_cluster,
                         cudaFuncAttributeNonPortableClusterSizeAllowed, 1);
    {
        cudaLaunchConfig_t cfg = {};
        cfg.gridDim  = dim3(64, 1, 1);
        cfg.blockDim = dim3(SCAN_THREADS, 1, 1);
        cfg.dynamicSmemBytes = SCAN_SMEM;
        cfg.stream = 0;
        cudaLaunchAttribute attrs[1];
        attrs[0].id = cudaLaunchAttributeClusterDimension;
        attrs[0].val.clusterDim.x = CL;
        attrs[0].val.clusterDim.y = 1;
        attrs[0].val.clusterDim.z = 1;
        cfg.attrs = attrs;
        cfg.numAttrs = 1;
        cudaLaunchKernelEx(&cfg, scan_cluster,
                           Uz, Ur, Uh, Wmem,
                           (const float*)pGz, (const float*)pGr,
                           (const float*)pGh, out);
    }

    (void)out_size;
}